// round 2
// baseline (speedup 1.0000x reference)
#include <cuda_runtime.h>
#include <cstdint>
#include <cstddef>

#define SEQ 2048
#define NHEADS 32

// scratch (device globals are the sanctioned no-alloc workaround)
__device__ float g_q[SEQ * 4096];
__device__ float g_k[SEQ * 1024];
__device__ float g_v[SEQ * 1024];
__device__ float g_sc[(size_t)NHEADS * SEQ * SEQ];  // 536 MB
__device__ float g_o[SEQ * 4096];

__device__ __forceinline__ void tf32_split(float v, uint32_t& h, uint32_t& l) {
    uint32_t hh;
    asm("cvt.rna.tf32.f32 %0, %1;" : "=r"(hh) : "f"(v));
    float r = v - __uint_as_float(hh);
    uint32_t ll;
    asm("cvt.rna.tf32.f32 %0, %1;" : "=r"(ll) : "f"(r));
    h = hh; l = ll;
}

__device__ __forceinline__ void mma_tf32(float* c, const uint32_t* a, const uint32_t* b) {
    asm volatile(
        "mma.sync.aligned.m16n8k8.row.col.f32.tf32.tf32.f32 "
        "{%0,%1,%2,%3}, {%4,%5,%6,%7}, {%8,%9}, {%0,%1,%2,%3};"
        : "+f"(c[0]), "+f"(c[1]), "+f"(c[2]), "+f"(c[3])
        : "r"(a[0]), "r"(a[1]), "r"(a[2]), "r"(a[3]), "r"(b[0]), "r"(b[1]));
}

#define CP16(saddr, gptr) \
    asm volatile("cp.async.cg.shared.global [%0], [%1], 16;" :: "r"(saddr), "l"(gptr))

// C[z] = alpha * op(A[z]) * op(B[z/bZdiv]); optional fused RoPE on output.
// A: row-major M x K (lda). B: TB ? (N x K row-major, i.e. B^T) : (K x N row-major).
// BM=BN=128, BK=32. 256 threads, 8 warps in 4(M) x 2(N), warp tile 32x64.
template <bool TB, bool ROPE>
__global__ void __launch_bounds__(256, 1) gemm_k(
    const float* __restrict__ A, int lda, size_t aZ,
    const float* __restrict__ B, int ldb, size_t bZ, int bZdiv,
    float* __restrict__ C, int ldc, size_t cZ,
    int K, float alpha,
    const float* __restrict__ cosp, const float* __restrict__ sinp)
{
    constexpr int ASTG = 128 * 36;                  // A stage floats ([m][36])
    constexpr int BSTG = TB ? 128 * 36 : 32 * 136;  // B stage floats
    extern __shared__ float sh[];
    float* As = sh;
    float* Bs = sh + 2 * ASTG;

    const int z = blockIdx.z;
    A += (size_t)z * aZ;
    B += (size_t)(z / bZdiv) * bZ;
    C += (size_t)z * cZ;

    const int tid = threadIdx.x;
    const int lane = tid & 31, warp = tid >> 5;
    const int g = lane >> 2, t4 = lane & 3;
    const int wm = (warp & 3) * 32, wn = (warp >> 2) * 64;
    const int bm = blockIdx.y * 128, bn = blockIdx.x * 128;

    uint32_t aBase, bBase;
    {
        uint32_t s;
        asm("{ .reg .u64 t; cvta.to.shared.u64 t, %1; cvt.u32.u64 %0, t; }"
            : "=r"(s) : "l"(sh));
        aBase = s;
        bBase = s + 2 * ASTG * 4;
    }

    float acc[2][8][4];
#pragma unroll
    for (int i = 0; i < 2; i++)
#pragma unroll
        for (int j = 0; j < 8; j++)
#pragma unroll
            for (int l = 0; l < 4; l++) acc[i][j][l] = 0.f;

    auto issue = [&](int st, int kt) {
#pragma unroll
        for (int j = 0; j < 4; j++) {
            int idx = tid + j * 256;
            int r = idx >> 3, c4 = (idx & 7) * 4;
            CP16(aBase + (uint32_t)((st * ASTG + r * 36 + c4) * 4),
                 A + (size_t)(bm + r) * lda + kt + c4);
        }
        if (TB) {
#pragma unroll
            for (int j = 0; j < 4; j++) {
                int idx = tid + j * 256;
                int r = idx >> 3, c4 = (idx & 7) * 4;
                CP16(bBase + (uint32_t)((st * BSTG + r * 36 + c4) * 4),
                     B + (size_t)(bn + r) * ldb + kt + c4);
            }
        } else {
#pragma unroll
            for (int j = 0; j < 4; j++) {
                int idx = tid + j * 256;
                int r = idx >> 5, c4 = (idx & 31) * 4;
                CP16(bBase + (uint32_t)((st * BSTG + r * 136 + c4) * 4),
                     B + (size_t)(kt + r) * ldb + bn + c4);
            }
        }
        asm volatile("cp.async.commit_group;" ::: "memory");
    };

    const int nK = K >> 5;
    issue(0, 0);
    for (int t = 0; t < nK; t++) {
        asm volatile("cp.async.wait_group 0;" ::: "memory");
        __syncthreads();
        if (t + 1 < nK) issue((t + 1) & 1, (t + 1) * 32);
        const float* As_ = As + (t & 1) * ASTG;
        const float* Bs_ = Bs + (t & 1) * BSTG;
#pragma unroll
        for (int k8 = 0; k8 < 4; k8++) {
            const int c0 = k8 * 8 + t4;
            uint32_t ah[2][4], al[2][4];
#pragma unroll
            for (int mi = 0; mi < 2; mi++) {
                int rb = wm + mi * 16 + g;
                tf32_split(As_[rb * 36 + c0],           ah[mi][0], al[mi][0]);
                tf32_split(As_[(rb + 8) * 36 + c0],     ah[mi][1], al[mi][1]);
                tf32_split(As_[rb * 36 + c0 + 4],       ah[mi][2], al[mi][2]);
                tf32_split(As_[(rb + 8) * 36 + c0 + 4], ah[mi][3], al[mi][3]);
            }
            uint32_t bh[8][2], bl[8][2];
#pragma unroll
            for (int ni = 0; ni < 8; ni++) {
                int cn = wn + ni * 8 + g;
                float y0, y1;
                if (TB) { y0 = Bs_[cn * 36 + c0];  y1 = Bs_[cn * 36 + c0 + 4]; }
                else    { y0 = Bs_[c0 * 136 + cn]; y1 = Bs_[(c0 + 4) * 136 + cn]; }
                tf32_split(y0, bh[ni][0], bl[ni][0]);
                tf32_split(y1, bh[ni][1], bl[ni][1]);
            }
#pragma unroll
            for (int mi = 0; mi < 2; mi++)
#pragma unroll
                for (int ni = 0; ni < 8; ni++) {
                    mma_tf32(acc[mi][ni], al[mi], bh[ni]);
                    mma_tf32(acc[mi][ni], ah[mi], bl[ni]);
                    mma_tf32(acc[mi][ni], ah[mi], bh[ni]);
                }
        }
    }

    // epilogue (+ optional RoPE: cols (2j, 2j+1) live in one thread's c0/c1)
#pragma unroll
    for (int mi = 0; mi < 2; mi++) {
        int rowg = bm + wm + mi * 16 + g;
#pragma unroll
        for (int ni = 0; ni < 8; ni++) {
            int colg = bn + wn + ni * 8 + 2 * t4;
            float c0 = acc[mi][ni][0] * alpha, c1 = acc[mi][ni][1] * alpha;
            float c2 = acc[mi][ni][2] * alpha, c3 = acc[mi][ni][3] * alpha;
            if (ROPE) {
                int i = (colg & 127) >> 1;
                float cs = cosp[rowg * 64 + i],      sn = sinp[rowg * 64 + i];
                float cs2 = cosp[(rowg + 8) * 64 + i], sn2 = sinp[(rowg + 8) * 64 + i];
                float o0 = c0 * cs - c1 * sn,  o1 = c0 * sn + c1 * cs;
                float o2 = c2 * cs2 - c3 * sn2, o3 = c2 * sn2 + c3 * cs2;
                c0 = o0; c1 = o1; c2 = o2; c3 = o3;
            }
            *(float2*)(C + (size_t)rowg * ldc + colg) = make_float2(c0, c1);
            *(float2*)(C + (size_t)(rowg + 8) * ldc + colg) = make_float2(c2, c3);
        }
    }
}

__global__ void __launch_bounds__(256) softmax_k(float* __restrict__ sbuf) {
    float* p = sbuf + (size_t)blockIdx.x * 2048;
    const int tid = threadIdx.x;
    float4 v0 = ((float4*)p)[tid];
    float4 v1 = ((float4*)p)[tid + 256];
    __shared__ float red[8];

    float mx = fmaxf(fmaxf(fmaxf(v0.x, v0.y), fmaxf(v0.z, v0.w)),
                     fmaxf(fmaxf(v1.x, v1.y), fmaxf(v1.z, v1.w)));
#pragma unroll
    for (int o = 16; o > 0; o >>= 1) mx = fmaxf(mx, __shfl_xor_sync(0xffffffffu, mx, o));
    if ((tid & 31) == 0) red[tid >> 5] = mx;
    __syncthreads();
    mx = red[0];
#pragma unroll
    for (int i = 1; i < 8; i++) mx = fmaxf(mx, red[i]);

    float e[8];
    e[0] = __expf(v0.x - mx); e[1] = __expf(v0.y - mx);
    e[2] = __expf(v0.z - mx); e[3] = __expf(v0.w - mx);
    e[4] = __expf(v1.x - mx); e[5] = __expf(v1.y - mx);
    e[6] = __expf(v1.z - mx); e[7] = __expf(v1.w - mx);
    float s = ((e[0] + e[1]) + (e[2] + e[3])) + ((e[4] + e[5]) + (e[6] + e[7]));
#pragma unroll
    for (int o = 16; o > 0; o >>= 1) s += __shfl_xor_sync(0xffffffffu, s, o);
    __syncthreads();  // red reuse
    if ((tid & 31) == 0) red[tid >> 5] = s;
    __syncthreads();
    s = red[0];
#pragma unroll
    for (int i = 1; i < 8; i++) s += red[i];
    float inv = 1.0f / s;

    ((float4*)p)[tid]       = make_float4(e[0] * inv, e[1] * inv, e[2] * inv, e[3] * inv);
    ((float4*)p)[tid + 256] = make_float4(e[4] * inv, e[5] * inv, e[6] * inv, e[7] * inv);
}

extern "C" void kernel_launch(void* const* d_in, const int* in_sizes, int n_in,
                              void* d_out, int out_size) {
    const float* x  = (const float*)d_in[0];
    const float* fc = (const float*)d_in[1];
    const float* fs = (const float*)d_in[2];
    const float* wq = (const float*)d_in[3];
    const float* wk = (const float*)d_in[4];
    const float* wv = (const float*)d_in[5];
    const float* wo = (const float*)d_in[6];
    float* out = (float*)d_out;

    float *q, *k, *v, *sb, *o;
    cudaGetSymbolAddress((void**)&q,  g_q);
    cudaGetSymbolAddress((void**)&k,  g_k);
    cudaGetSymbolAddress((void**)&v,  g_v);
    cudaGetSymbolAddress((void**)&sb, g_sc);
    cudaGetSymbolAddress((void**)&o,  g_o);

    const int SM = 73728;
    cudaFuncSetAttribute(gemm_k<false, true>,  cudaFuncAttributeMaxDynamicSharedMemorySize, SM);
    cudaFuncSetAttribute(gemm_k<false, false>, cudaFuncAttributeMaxDynamicSharedMemorySize, SM);
    cudaFuncSetAttribute(gemm_k<true,  false>, cudaFuncAttributeMaxDynamicSharedMemorySize, SM);

    const dim3 blk(256);
    const size_t SS = (size_t)SEQ * SEQ;
    const float scale = 0.08838834764831845f;  // 1/sqrt(128)

    // Q/K projections with fused RoPE; V plain
    gemm_k<false, true ><<<dim3(32, 16, 1), blk, SM>>>(x, 4096, 0, wq, 4096, 0, 1, q, 4096, 0, 4096, 1.f, fc, fs);
    gemm_k<false, true ><<<dim3( 8, 16, 1), blk, SM>>>(x, 4096, 0, wk, 1024, 0, 1, k, 1024, 0, 4096, 1.f, fc, fs);
    gemm_k<false, false><<<dim3( 8, 16, 1), blk, SM>>>(x, 4096, 0, wv, 1024, 0, 1, v, 1024, 0, 4096, 1.f, nullptr, nullptr);
    // scores[h] = scale * q_h @ k_{h/4}^T   (32 heads via blockIdx.z)
    gemm_k<true,  false><<<dim3(16, 16, NHEADS), blk, SM>>>(q, 4096, 128, k, 1024, 128, 4, sb, 2048, SS, 128, scale, nullptr, nullptr);
    // row softmax over 32*2048 rows of 2048
    softmax_k<<<NHEADS * SEQ, 256>>>(sb);
    // O[h] = P_h @ v_{h/4}
    gemm_k<false, false><<<dim3(1, 16, NHEADS), blk, SM>>>(sb, 2048, SS, v, 1024, 128, 4, o, 4096, 128, 2048, 1.f, nullptr, nullptr);
    // final = O @ wo
    gemm_k<false, false><<<dim3(32, 16, 1), blk, SM>>>(o, 4096, 0, wo, 4096, 0, 1, out, 4096, 0, 4096, 1.f, nullptr, nullptr);
}

// round 5
// speedup vs baseline: 1.7488x; 1.7488x over previous
#include <cuda_runtime.h>
#include <cstdint>
#include <cstddef>

#define SEQ 2048
#define NHEADS 32

__device__ float g_q[SEQ * 4096];
__device__ float g_k[SEQ * 1024];
__device__ float g_v[SEQ * 1024];
__device__ float g_sc[(size_t)NHEADS * SEQ * SEQ];
__device__ float g_o[SEQ * 4096];

// round-to-nearest bf16 hi/lo split of a float4; h0={y,x} packed, h1={w,z}
__device__ __forceinline__ void split4(float4 f, uint32_t& h0, uint32_t& h1,
                                       uint32_t& l0, uint32_t& l1) {
    asm("cvt.rn.bf16x2.f32 %0, %1, %2;" : "=r"(h0) : "f"(f.y), "f"(f.x));
    asm("cvt.rn.bf16x2.f32 %0, %1, %2;" : "=r"(h1) : "f"(f.w), "f"(f.z));
    float hx = __uint_as_float(h0 << 16), hy = __uint_as_float(h0 & 0xFFFF0000u);
    float hz = __uint_as_float(h1 << 16), hw = __uint_as_float(h1 & 0xFFFF0000u);
    float lx = f.x - hx, ly = f.y - hy, lz = f.z - hz, lw = f.w - hw;
    asm("cvt.rn.bf16x2.f32 %0, %1, %2;" : "=r"(l0) : "f"(ly), "f"(lx));
    asm("cvt.rn.bf16x2.f32 %0, %1, %2;" : "=r"(l1) : "f"(lw), "f"(lz));
}

#define MMA16816(C, A0, A1, A2, A3, B0, B1)                                         \
    asm volatile(                                                                   \
        "mma.sync.aligned.m16n8k16.row.col.f32.bf16.bf16.f32 "                      \
        "{%0,%1,%2,%3},{%4,%5,%6,%7},{%8,%9},{%0,%1,%2,%3};"                        \
        : "+f"((C)[0]), "+f"((C)[1]), "+f"((C)[2]), "+f"((C)[3])                    \
        : "r"(A0), "r"(A1), "r"(A2), "r"(A3), "r"(B0), "r"(B1))

#define LDSM4(R0, R1, R2, R3, ADDR)                                                 \
    asm volatile("ldmatrix.sync.aligned.m8n8.x4.shared.b16 {%0,%1,%2,%3},[%4];"     \
                 : "=r"(R0), "=r"(R1), "=r"(R2), "=r"(R3) : "r"(ADDR))

#define LDSM4T(R0, R1, R2, R3, ADDR)                                                \
    asm volatile("ldmatrix.sync.aligned.m8n8.x4.trans.shared.b16 {%0,%1,%2,%3},[%4];" \
                 : "=r"(R0), "=r"(R1), "=r"(R2), "=r"(R3) : "r"(ADDR))

#define STS64(ADDR, V0, V1)                                                         \
    asm volatile("st.shared.v2.b32 [%0],{%1,%2};" :: "r"(ADDR), "r"(V0), "r"(V1))

// Smem layout per stage (bytes): Ahi 0 | Alo 10240 | Bhi 20480 | Blo 30720
// A: 128 rows x 32 k bf16, pitch 80B (16*5, conflict-free for LDSM).
// B (TB):  128 n-rows x 32 k bf16, pitch 80B.
// B (!TB): 32 k-rows x 128 n bf16, pitch 272B (16*17).
#define STG_BYTES 40960
#define ALO_OFF   10240u
#define BHI_OFF   20480u
#define BLO_OFF   30720u

// C[z] = alpha * op(A[z]) * op(B[z/bZdiv]); optional fused RoPE on output.
// BM=BN=128, BK=32. 256 threads, warps 4(M) x 2(N), warp tile 32x64. bf16x3.
template <bool TB, bool ROPE>
__global__ void __launch_bounds__(256, 1) gemm_k(
    const float* __restrict__ A, int lda, size_t aZ,
    const float* __restrict__ B, int ldb, size_t bZ, int bZdiv,
    float* __restrict__ C, int ldc, size_t cZ,
    int K, float alpha,
    const float* __restrict__ cosp, const float* __restrict__ sinp)
{
    extern __shared__ char sh[];
    const int z = blockIdx.z;
    A += (size_t)z * aZ;
    B += (size_t)(z / bZdiv) * bZ;
    C += (size_t)z * cZ;

    const int tid = threadIdx.x;
    const int lane = tid & 31, warp = tid >> 5;
    const int g = lane >> 2, t4 = lane & 3;
    const int wm = (warp & 3) * 32, wn = (warp >> 2) * 64;
    const int bm = blockIdx.y * 128, bn = blockIdx.x * 128;

    uint32_t sbase;
    asm("{ .reg .u64 t; cvta.to.shared.u64 t, %1; cvt.u32.u64 %0, t; }"
        : "=r"(sbase) : "l"(sh));

    // ---- per-thread gmem coords + smem store offsets ----
    const float* pA[4];
    const float* pB[4];
    uint32_t sA[4], sB[4];
#pragma unroll
    for (int j = 0; j < 4; j++) {
        int idx = tid + j * 256;
        int r = idx >> 3, c4 = idx & 7;               // A: row r, k-f4 c4
        pA[j] = A + (size_t)(bm + r) * lda + c4 * 4;
        sA[j] = sbase + (uint32_t)(r * 80 + c4 * 8);
        if (TB) {
            pB[j] = B + (size_t)(bn + r) * ldb + c4 * 4;
            sB[j] = sbase + BHI_OFF + (uint32_t)(r * 80 + c4 * 8);
        } else {
            int kr = idx >> 5, n4 = idx & 31;          // B: k-row kr, n-f4 n4
            pB[j] = B + (size_t)kr * ldb + bn + n4 * 4;
            sB[j] = sbase + BHI_OFF + (uint32_t)(kr * 272 + n4 * 8);
        }
    }

    // ---- ldmatrix lane addresses (stage/kb added later) ----
    const int lr = (lane & 7) + ((lane >> 3) & 1) * 8;
    const int lk = lane >> 4;
    uint32_t aAddr[2], bAddr[4];
#pragma unroll
    for (int mi = 0; mi < 2; mi++)
        aAddr[mi] = sbase + (uint32_t)((wm + mi * 16 + lr) * 80 + lk * 16);
#pragma unroll
    for (int nb = 0; nb < 4; nb++) {
        if (TB) {
            bAddr[nb] = sbase + BHI_OFF + (uint32_t)((wn + nb * 16 + lr) * 80 + lk * 16);
        } else {
            int kk = (lane & 7) + lk * 8;
            int nc = (wn >> 3) + nb * 2 + ((lane >> 3) & 1);
            bAddr[nb] = sbase + BHI_OFF + (uint32_t)(kk * 272 + nc * 16);
        }
    }

    float acc[2][8][4];
#pragma unroll
    for (int i = 0; i < 2; i++)
#pragma unroll
        for (int j = 0; j < 8; j++)
#pragma unroll
            for (int l = 0; l < 4; l++) acc[i][j][l] = 0.f;

    float4 ra[4], rb[4];
    auto ldg = [&]() {
#pragma unroll
        for (int j = 0; j < 4; j++) {
            ra[j] = *(const float4*)pA[j];
            rb[j] = *(const float4*)pB[j];
            pA[j] += 32;
            pB[j] += TB ? 32 : (size_t)32 * ldb;
        }
    };
    auto sts = [&](int st) {
        uint32_t so = (uint32_t)st * STG_BYTES;
#pragma unroll
        for (int j = 0; j < 4; j++) {
            uint32_t h0, h1, l0, l1;
            split4(ra[j], h0, h1, l0, l1);
            STS64(sA[j] + so, h0, h1);
            STS64(sA[j] + so + ALO_OFF, l0, l1);
            split4(rb[j], h0, h1, l0, l1);
            STS64(sB[j] + so, h0, h1);
            STS64(sB[j] + so + (BLO_OFF - BHI_OFF), l0, l1);
        }
    };

    const int nK = K >> 5;
    ldg();
    sts(0);
    __syncthreads();

    for (int t = 0; t < nK; t++) {
        const bool more = (t + 1 < nK);
        if (more) ldg();
        const uint32_t so = (uint32_t)(t & 1) * STG_BYTES;
#pragma unroll
        for (int kb = 0; kb < 2; kb++) {
            uint32_t AH[2][4], AL[2][4], BH[8][2], BL[8][2];
#pragma unroll
            for (int mi = 0; mi < 2; mi++) {
                uint32_t ad = aAddr[mi] + so + kb * 32;
                LDSM4(AH[mi][0], AH[mi][1], AH[mi][2], AH[mi][3], ad);
                LDSM4(AL[mi][0], AL[mi][1], AL[mi][2], AL[mi][3], ad + ALO_OFF);
            }
#pragma unroll
            for (int nb = 0; nb < 4; nb++) {
                uint32_t q0, q1, q2, q3;
                if (TB) {
                    uint32_t bd = bAddr[nb] + so + kb * 32;
                    LDSM4(q0, q1, q2, q3, bd);
                    BH[2 * nb][0] = q0; BH[2 * nb][1] = q2;
                    BH[2 * nb + 1][0] = q1; BH[2 * nb + 1][1] = q3;
                    LDSM4(q0, q1, q2, q3, bd + (BLO_OFF - BHI_OFF));
                    BL[2 * nb][0] = q0; BL[2 * nb][1] = q2;
                    BL[2 * nb + 1][0] = q1; BL[2 * nb + 1][1] = q3;
                } else {
                    uint32_t bd = bAddr[nb] + so + kb * (16 * 272);
                    LDSM4T(q0, q1, q2, q3, bd);
                    BH[2 * nb][0] = q0; BH[2 * nb][1] = q2;
                    BH[2 * nb + 1][0] = q1; BH[2 * nb + 1][1] = q3;
                    LDSM4T(q0, q1, q2, q3, bd + (BLO_OFF - BHI_OFF));
                    BL[2 * nb][0] = q0; BL[2 * nb][1] = q2;
                    BL[2 * nb + 1][0] = q1; BL[2 * nb + 1][1] = q3;
                }
            }
#pragma unroll
            for (int mi = 0; mi < 2; mi++)
#pragma unroll
                for (int ni = 0; ni < 8; ni++) {
                    MMA16816(acc[mi][ni], AH[mi][0], AH[mi][1], AH[mi][2], AH[mi][3],
                             BL[ni][0], BL[ni][1]);
                    MMA16816(acc[mi][ni], AL[mi][0], AL[mi][1], AL[mi][2], AL[mi][3],
                             BH[ni][0], BH[ni][1]);
                    MMA16816(acc[mi][ni], AH[mi][0], AH[mi][1], AH[mi][2], AH[mi][3],
                             BH[ni][0], BH[ni][1]);
                }
        }
        if (more) sts((t + 1) & 1);
        __syncthreads();
    }

    // epilogue (+ optional RoPE: cols (2j,2j+1) live in one thread's c0/c1)
#pragma unroll
    for (int mi = 0; mi < 2; mi++) {
        int rowg = bm + wm + mi * 16 + g;
#pragma unroll
        for (int ni = 0; ni < 8; ni++) {
            int colg = bn + wn + ni * 8 + 2 * t4;
            float c0 = acc[mi][ni][0] * alpha, c1 = acc[mi][ni][1] * alpha;
            float c2 = acc[mi][ni][2] * alpha, c3 = acc[mi][ni][3] * alpha;
            if (ROPE) {
                int i = (colg & 127) >> 1;
                float cs = cosp[rowg * 64 + i], sn = sinp[rowg * 64 + i];
                float cs2 = cosp[(rowg + 8) * 64 + i], sn2 = sinp[(rowg + 8) * 64 + i];
                float o0 = c0 * cs - c1 * sn, o1 = c0 * sn + c1 * cs;
                float o2 = c2 * cs2 - c3 * sn2, o3 = c2 * sn2 + c3 * cs2;
                c0 = o0; c1 = o1; c2 = o2; c3 = o3;
            }
            *(float2*)(C + (size_t)rowg * ldc + colg) = make_float2(c0, c1);
            *(float2*)(C + (size_t)(rowg + 8) * ldc + colg) = make_float2(c2, c3);
        }
    }
}

__global__ void __launch_bounds__(256) softmax_k(float* __restrict__ sbuf) {
    float* p = sbuf + (size_t)blockIdx.x * 2048;
    const int tid = threadIdx.x;
    float4 v0 = ((float4*)p)[tid];
    float4 v1 = ((float4*)p)[tid + 256];
    __shared__ float red[8];

    float mx = fmaxf(fmaxf(fmaxf(v0.x, v0.y), fmaxf(v0.z, v0.w)),
                     fmaxf(fmaxf(v1.x, v1.y), fmaxf(v1.z, v1.w)));
#pragma unroll
    for (int o = 16; o > 0; o >>= 1) mx = fmaxf(mx, __shfl_xor_sync(0xffffffffu, mx, o));
    if ((tid & 31) == 0) red[tid >> 5] = mx;
    __syncthreads();
    mx = red[0];
#pragma unroll
    for (int i = 1; i < 8; i++) mx = fmaxf(mx, red[i]);

    float e[8];
    e[0] = __expf(v0.x - mx); e[1] = __expf(v0.y - mx);
    e[2] = __expf(v0.z - mx); e[3] = __expf(v0.w - mx);
    e[4] = __expf(v1.x - mx); e[5] = __expf(v1.y - mx);
    e[6] = __expf(v1.z - mx); e[7] = __expf(v1.w - mx);
    float s = ((e[0] + e[1]) + (e[2] + e[3])) + ((e[4] + e[5]) + (e[6] + e[7]));
#pragma unroll
    for (int o = 16; o > 0; o >>= 1) s += __shfl_xor_sync(0xffffffffu, s, o);
    __syncthreads();
    if ((tid & 31) == 0) red[tid >> 5] = s;
    __syncthreads();
    s = red[0];
#pragma unroll
    for (int i = 1; i < 8; i++) s += red[i];
    float inv = 1.0f / s;

    ((float4*)p)[tid]       = make_float4(e[0] * inv, e[1] * inv, e[2] * inv, e[3] * inv);
    ((float4*)p)[tid + 256] = make_float4(e[4] * inv, e[5] * inv, e[6] * inv, e[7] * inv);
}

extern "C" void kernel_launch(void* const* d_in, const int* in_sizes, int n_in,
                              void* d_out, int out_size) {
    const float* x  = (const float*)d_in[0];
    const float* fc = (const float*)d_in[1];
    const float* fs = (const float*)d_in[2];
    const float* wq = (const float*)d_in[3];
    const float* wk = (const float*)d_in[4];
    const float* wv = (const float*)d_in[5];
    const float* wo = (const float*)d_in[6];
    float* out = (float*)d_out;

    float *q, *k, *v, *sb, *o;
    cudaGetSymbolAddress((void**)&q,  g_q);
    cudaGetSymbolAddress((void**)&k,  g_k);
    cudaGetSymbolAddress((void**)&v,  g_v);
    cudaGetSymbolAddress((void**)&sb, g_sc);
    cudaGetSymbolAddress((void**)&o,  g_o);

    const int SM = 2 * STG_BYTES;  // 81920
    cudaFuncSetAttribute(gemm_k<false, true>,  cudaFuncAttributeMaxDynamicSharedMemorySize, SM);
    cudaFuncSetAttribute(gemm_k<false, false>, cudaFuncAttributeMaxDynamicSharedMemorySize, SM);
    cudaFuncSetAttribute(gemm_k<true,  false>, cudaFuncAttributeMaxDynamicSharedMemorySize, SM);

    const dim3 blk(256);
    const size_t SS = (size_t)SEQ * SEQ;
    const float scale = 0.08838834764831845f;  // 1/sqrt(128)

    gemm_k<false, true ><<<dim3(32, 16, 1), blk, SM>>>(x, 4096, 0, wq, 4096, 0, 1, q, 4096, 0, 4096, 1.f, fc, fs);
    gemm_k<false, true ><<<dim3( 8, 16, 1), blk, SM>>>(x, 4096, 0, wk, 1024, 0, 1, k, 1024, 0, 4096, 1.f, fc, fs);
    gemm_k<false, false><<<dim3( 8, 16, 1), blk, SM>>>(x, 4096, 0, wv, 1024, 0, 1, v, 1024, 0, 4096, 1.f, nullptr, nullptr);
    gemm_k<true,  false><<<dim3(16, 16, NHEADS), blk, SM>>>(q, 4096, 128, k, 1024, 128, 4, sb, 2048, SS, 128, scale, nullptr, nullptr);
    softmax_k<<<NHEADS * SEQ, 256>>>(sb);
    gemm_k<false, false><<<dim3(1, 16, NHEADS), blk, SM>>>(sb, 2048, SS, v, 1024, 128, 4, o, 4096, 128, 2048, 1.f, nullptr, nullptr);
    gemm_k<false, false><<<dim3(32, 16, 1), blk, SM>>>(o, 4096, 0, wo, 4096, 0, 1, out, 4096, 0, 4096, 1.f, nullptr, nullptr);
}

// round 6
// speedup vs baseline: 1.8370x; 1.0504x over previous
#include <cuda_runtime.h>
#include <cstdint>
#include <cstddef>

#define SEQ 2048
#define NHEADS 32

__device__ float g_q[SEQ * 4096];
__device__ float g_k[SEQ * 1024];
__device__ float g_v[SEQ * 1024];
__device__ float g_sc[(size_t)NHEADS * SEQ * SEQ];
__device__ float g_o[SEQ * 4096];

// round-to-nearest bf16 hi/lo split of a float4; h0={y,x} packed, h1={w,z}
__device__ __forceinline__ void split4(float4 f, uint32_t& h0, uint32_t& h1,
                                       uint32_t& l0, uint32_t& l1) {
    asm("cvt.rn.bf16x2.f32 %0, %1, %2;" : "=r"(h0) : "f"(f.y), "f"(f.x));
    asm("cvt.rn.bf16x2.f32 %0, %1, %2;" : "=r"(h1) : "f"(f.w), "f"(f.z));
    float hx = __uint_as_float(h0 << 16), hy = __uint_as_float(h0 & 0xFFFF0000u);
    float hz = __uint_as_float(h1 << 16), hw = __uint_as_float(h1 & 0xFFFF0000u);
    float lx = f.x - hx, ly = f.y - hy, lz = f.z - hz, lw = f.w - hw;
    asm("cvt.rn.bf16x2.f32 %0, %1, %2;" : "=r"(l0) : "f"(ly), "f"(lx));
    asm("cvt.rn.bf16x2.f32 %0, %1, %2;" : "=r"(l1) : "f"(lw), "f"(lz));
}

#define MMA16816(C, A0, A1, A2, A3, B0, B1)                                         \
    asm volatile(                                                                   \
        "mma.sync.aligned.m16n8k16.row.col.f32.bf16.bf16.f32 "                      \
        "{%0,%1,%2,%3},{%4,%5,%6,%7},{%8,%9},{%0,%1,%2,%3};"                        \
        : "+f"((C)[0]), "+f"((C)[1]), "+f"((C)[2]), "+f"((C)[3])                    \
        : "r"(A0), "r"(A1), "r"(A2), "r"(A3), "r"(B0), "r"(B1))

#define LDSM4(R0, R1, R2, R3, ADDR)                                                 \
    asm volatile("ldmatrix.sync.aligned.m8n8.x4.shared.b16 {%0,%1,%2,%3},[%4];"     \
                 : "=r"(R0), "=r"(R1), "=r"(R2), "=r"(R3) : "r"(ADDR))

#define LDSM4T(R0, R1, R2, R3, ADDR)                                                \
    asm volatile("ldmatrix.sync.aligned.m8n8.x4.trans.shared.b16 {%0,%1,%2,%3},[%4];" \
                 : "=r"(R0), "=r"(R1), "=r"(R2), "=r"(R3) : "r"(ADDR))

#define STS64(ADDR, V0, V1)                                                         \
    asm volatile("st.shared.v2.b32 [%0],{%1,%2};" :: "r"(ADDR), "r"(V0), "r"(V1))

// Smem layout per stage (bytes): Ahi 0 | Alo 10240 | Bhi 20480 | Blo 30720
// A: 128 rows x 32 k bf16, pitch 80B (16*5, conflict-free for LDSM).
// B (TB):  128 n-rows x 32 k bf16, pitch 80B.
// B (!TB): 32 k-rows x 128 n bf16, pitch 272B (16*17).
#define STG_BYTES 40960
#define ALO_OFF   10240u
#define BHI_OFF   20480u
#define BLO_OFF   30720u

// C[z] = alpha * op(A[z]) * op(B[z/bZdiv]); optional fused RoPE on output.
// BM=BN=128, BK=32. 512 threads, 16 warps in 4(M) x 4(N), warp tile 32x32. bf16x3.
template <bool TB, bool ROPE>
__global__ void __launch_bounds__(512, 1) gemm_k(
    const float* __restrict__ A, int lda, size_t aZ,
    const float* __restrict__ B, int ldb, size_t bZ, int bZdiv,
    float* __restrict__ C, int ldc, size_t cZ,
    int K, float alpha,
    const float* __restrict__ cosp, const float* __restrict__ sinp)
{
    extern __shared__ char sh[];
    const int z = blockIdx.z;
    A += (size_t)z * aZ;
    B += (size_t)(z / bZdiv) * bZ;
    C += (size_t)z * cZ;

    const int tid = threadIdx.x;
    const int lane = tid & 31, warp = tid >> 5;
    const int g = lane >> 2, t4 = lane & 3;
    const int wm = (warp & 3) * 32, wn = (warp >> 2) * 32;
    const int bm = blockIdx.y * 128, bn = blockIdx.x * 128;

    uint32_t sbase;
    asm("{ .reg .u64 t; cvta.to.shared.u64 t, %1; cvt.u32.u64 %0, t; }"
        : "=r"(sbase) : "l"(sh));

    // ---- per-thread gmem coords + smem store offsets (2 chunks per thread) ----
    const float* pA[2];
    const float* pB[2];
    uint32_t sA[2], sB[2];
#pragma unroll
    for (int j = 0; j < 2; j++) {
        int idx = tid + j * 512;
        int r = idx >> 3, c4 = idx & 7;               // A: row r, k-f4 c4
        pA[j] = A + (size_t)(bm + r) * lda + c4 * 4;
        sA[j] = sbase + (uint32_t)(r * 80 + c4 * 8);
        if (TB) {
            pB[j] = B + (size_t)(bn + r) * ldb + c4 * 4;
            sB[j] = sbase + BHI_OFF + (uint32_t)(r * 80 + c4 * 8);
        } else {
            int kr = idx >> 5, n4 = idx & 31;          // B: k-row kr, n-f4 n4
            pB[j] = B + (size_t)kr * ldb + bn + n4 * 4;
            sB[j] = sbase + BHI_OFF + (uint32_t)(kr * 272 + n4 * 8);
        }
    }

    // ---- ldmatrix lane addresses (stage/kb added later) ----
    const int lr = (lane & 7) + ((lane >> 3) & 1) * 8;
    const int lk = lane >> 4;
    uint32_t aAddr[2], bAddr[2];
#pragma unroll
    for (int mi = 0; mi < 2; mi++)
        aAddr[mi] = sbase + (uint32_t)((wm + mi * 16 + lr) * 80 + lk * 16);
#pragma unroll
    for (int nb = 0; nb < 2; nb++) {
        if (TB) {
            bAddr[nb] = sbase + BHI_OFF + (uint32_t)((wn + nb * 16 + lr) * 80 + lk * 16);
        } else {
            int kk = (lane & 7) + lk * 8;
            int nc = (wn >> 3) + nb * 2 + ((lane >> 3) & 1);
            bAddr[nb] = sbase + BHI_OFF + (uint32_t)(kk * 272 + nc * 16);
        }
    }

    float acc[2][4][4];
#pragma unroll
    for (int i = 0; i < 2; i++)
#pragma unroll
        for (int j = 0; j < 4; j++)
#pragma unroll
            for (int l = 0; l < 4; l++) acc[i][j][l] = 0.f;

    float4 ra[2], rb[2];
    auto ldg = [&]() {
#pragma unroll
        for (int j = 0; j < 2; j++) {
            ra[j] = *(const float4*)pA[j];
            rb[j] = *(const float4*)pB[j];
            pA[j] += 32;
            pB[j] += TB ? 32 : (size_t)32 * ldb;
        }
    };
    auto sts = [&](int st) {
        uint32_t so = (uint32_t)st * STG_BYTES;
#pragma unroll
        for (int j = 0; j < 2; j++) {
            uint32_t h0, h1, l0, l1;
            split4(ra[j], h0, h1, l0, l1);
            STS64(sA[j] + so, h0, h1);
            STS64(sA[j] + so + ALO_OFF, l0, l1);
            split4(rb[j], h0, h1, l0, l1);
            STS64(sB[j] + so, h0, h1);
            STS64(sB[j] + so + (BLO_OFF - BHI_OFF), l0, l1);
        }
    };

    const int nK = K >> 5;
    ldg();
    sts(0);
    __syncthreads();

    for (int t = 0; t < nK; t++) {
        const bool more = (t + 1 < nK);
        if (more) ldg();
        const uint32_t so = (uint32_t)(t & 1) * STG_BYTES;
#pragma unroll
        for (int kb = 0; kb < 2; kb++) {
            uint32_t AH[2][4], AL[2][4], BH[4][2], BL[4][2];
#pragma unroll
            for (int mi = 0; mi < 2; mi++) {
                uint32_t ad = aAddr[mi] + so + kb * 32;
                LDSM4(AH[mi][0], AH[mi][1], AH[mi][2], AH[mi][3], ad);
                LDSM4(AL[mi][0], AL[mi][1], AL[mi][2], AL[mi][3], ad + ALO_OFF);
            }
#pragma unroll
            for (int nb = 0; nb < 2; nb++) {
                uint32_t q0, q1, q2, q3;
                if (TB) {
                    uint32_t bd = bAddr[nb] + so + kb * 32;
                    LDSM4(q0, q1, q2, q3, bd);
                    BH[2 * nb][0] = q0; BH[2 * nb][1] = q2;
                    BH[2 * nb + 1][0] = q1; BH[2 * nb + 1][1] = q3;
                    LDSM4(q0, q1, q2, q3, bd + (BLO_OFF - BHI_OFF));
                    BL[2 * nb][0] = q0; BL[2 * nb][1] = q2;
                    BL[2 * nb + 1][0] = q1; BL[2 * nb + 1][1] = q3;
                } else {
                    uint32_t bd = bAddr[nb] + so + kb * (16 * 272);
                    LDSM4T(q0, q1, q2, q3, bd);
                    BH[2 * nb][0] = q0; BH[2 * nb][1] = q2;
                    BH[2 * nb + 1][0] = q1; BH[2 * nb + 1][1] = q3;
                    LDSM4T(q0, q1, q2, q3, bd + (BLO_OFF - BHI_OFF));
                    BL[2 * nb][0] = q0; BL[2 * nb][1] = q2;
                    BL[2 * nb + 1][0] = q1; BL[2 * nb + 1][1] = q3;
                }
            }
#pragma unroll
            for (int mi = 0; mi < 2; mi++)
#pragma unroll
                for (int ni = 0; ni < 4; ni++) {
                    MMA16816(acc[mi][ni], AH[mi][0], AH[mi][1], AH[mi][2], AH[mi][3],
                             BL[ni][0], BL[ni][1]);
                    MMA16816(acc[mi][ni], AL[mi][0], AL[mi][1], AL[mi][2], AL[mi][3],
                             BH[ni][0], BH[ni][1]);
                    MMA16816(acc[mi][ni], AH[mi][0], AH[mi][1], AH[mi][2], AH[mi][3],
                             BH[ni][0], BH[ni][1]);
                }
        }
        if (more) sts((t + 1) & 1);
        __syncthreads();
    }

    // epilogue (+ optional RoPE: cols (2j,2j+1) live in one thread's c0/c1)
#pragma unroll
    for (int mi = 0; mi < 2; mi++) {
        int rowg = bm + wm + mi * 16 + g;
#pragma unroll
        for (int ni = 0; ni < 4; ni++) {
            int colg = bn + wn + ni * 8 + 2 * t4;
            float c0 = acc[mi][ni][0] * alpha, c1 = acc[mi][ni][1] * alpha;
            float c2 = acc[mi][ni][2] * alpha, c3 = acc[mi][ni][3] * alpha;
            if (ROPE) {
                int i = (colg & 127) >> 1;
                float cs = cosp[rowg * 64 + i], sn = sinp[rowg * 64 + i];
                float cs2 = cosp[(rowg + 8) * 64 + i], sn2 = sinp[(rowg + 8) * 64 + i];
                float o0 = c0 * cs - c1 * sn, o1 = c0 * sn + c1 * cs;
                float o2 = c2 * cs2 - c3 * sn2, o3 = c2 * sn2 + c3 * cs2;
                c0 = o0; c1 = o1; c2 = o2; c3 = o3;
            }
            *(float2*)(C + (size_t)rowg * ldc + colg) = make_float2(c0, c1);
            *(float2*)(C + (size_t)(rowg + 8) * ldc + colg) = make_float2(c2, c3);
        }
    }
}

__global__ void __launch_bounds__(256) softmax_k(float* __restrict__ sbuf) {
    float* p = sbuf + (size_t)blockIdx.x * 2048;
    const int tid = threadIdx.x;
    float4 v0 = ((float4*)p)[tid];
    float4 v1 = ((float4*)p)[tid + 256];
    __shared__ float red[8];

    float mx = fmaxf(fmaxf(fmaxf(v0.x, v0.y), fmaxf(v0.z, v0.w)),
                     fmaxf(fmaxf(v1.x, v1.y), fmaxf(v1.z, v1.w)));
#pragma unroll
    for (int o = 16; o > 0; o >>= 1) mx = fmaxf(mx, __shfl_xor_sync(0xffffffffu, mx, o));
    if ((tid & 31) == 0) red[tid >> 5] = mx;
    __syncthreads();
    mx = red[0];
#pragma unroll
    for (int i = 1; i < 8; i++) mx = fmaxf(mx, red[i]);

    float e[8];
    e[0] = __expf(v0.x - mx); e[1] = __expf(v0.y - mx);
    e[2] = __expf(v0.z - mx); e[3] = __expf(v0.w - mx);
    e[4] = __expf(v1.x - mx); e[5] = __expf(v1.y - mx);
    e[6] = __expf(v1.z - mx); e[7] = __expf(v1.w - mx);
    float s = ((e[0] + e[1]) + (e[2] + e[3])) + ((e[4] + e[5]) + (e[6] + e[7]));
#pragma unroll
    for (int o = 16; o > 0; o >>= 1) s += __shfl_xor_sync(0xffffffffu, s, o);
    __syncthreads();
    if ((tid & 31) == 0) red[tid >> 5] = s;
    __syncthreads();
    s = red[0];
#pragma unroll
    for (int i = 1; i < 8; i++) s += red[i];
    float inv = 1.0f / s;

    ((float4*)p)[tid]       = make_float4(e[0] * inv, e[1] * inv, e[2] * inv, e[3] * inv);
    ((float4*)p)[tid + 256] = make_float4(e[4] * inv, e[5] * inv, e[6] * inv, e[7] * inv);
}

extern "C" void kernel_launch(void* const* d_in, const int* in_sizes, int n_in,
                              void* d_out, int out_size) {
    const float* x  = (const float*)d_in[0];
    const float* fc = (const float*)d_in[1];
    const float* fs = (const float*)d_in[2];
    const float* wq = (const float*)d_in[3];
    const float* wk = (const float*)d_in[4];
    const float* wv = (const float*)d_in[5];
    const float* wo = (const float*)d_in[6];
    float* out = (float*)d_out;

    float *q, *k, *v, *sb, *o;
    cudaGetSymbolAddress((void**)&q,  g_q);
    cudaGetSymbolAddress((void**)&k,  g_k);
    cudaGetSymbolAddress((void**)&v,  g_v);
    cudaGetSymbolAddress((void**)&sb, g_sc);
    cudaGetSymbolAddress((void**)&o,  g_o);

    const int SM = 2 * STG_BYTES;  // 81920
    cudaFuncSetAttribute(gemm_k<false, true>,  cudaFuncAttributeMaxDynamicSharedMemorySize, SM);
    cudaFuncSetAttribute(gemm_k<false, false>, cudaFuncAttributeMaxDynamicSharedMemorySize, SM);
    cudaFuncSetAttribute(gemm_k<true,  false>, cudaFuncAttributeMaxDynamicSharedMemorySize, SM);

    const dim3 blk(512);
    const size_t SS = (size_t)SEQ * SEQ;
    const float scale = 0.08838834764831845f;  // 1/sqrt(128)

    gemm_k<false, true ><<<dim3(32, 16, 1), blk, SM>>>(x, 4096, 0, wq, 4096, 0, 1, q, 4096, 0, 4096, 1.f, fc, fs);
    gemm_k<false, true ><<<dim3( 8, 16, 1), blk, SM>>>(x, 4096, 0, wk, 1024, 0, 1, k, 1024, 0, 4096, 1.f, fc, fs);
    gemm_k<false, false><<<dim3( 8, 16, 1), blk, SM>>>(x, 4096, 0, wv, 1024, 0, 1, v, 1024, 0, 4096, 1.f, nullptr, nullptr);
    gemm_k<true,  false><<<dim3(16, 16, NHEADS), blk, SM>>>(q, 4096, 128, k, 1024, 128, 4, sb, 2048, SS, 128, scale, nullptr, nullptr);
    softmax_k<<<NHEADS * SEQ, 256>>>(sb);
    gemm_k<false, false><<<dim3(1, 16, NHEADS), blk, SM>>>(sb, 2048, SS, v, 1024, 128, 4, o, 4096, 128, 2048, 1.f, nullptr, nullptr);
    gemm_k<false, false><<<dim3(32, 16, 1), blk, SM>>>(o, 4096, 0, wo, 4096, 0, 1, out, 4096, 0, 4096, 1.f, nullptr, nullptr);
}

// round 9
// speedup vs baseline: 2.3919x; 1.3021x over previous
#include <cuda_runtime.h>
#include <cuda_fp16.h>
#include <cstdint>
#include <cstddef>

#define SEQ 2048
#define NHEADS 32

__device__ __half g_qh[SEQ * 4096];
__device__ __half g_kh[SEQ * 1024];
__device__ __half g_vh[SEQ * 1024];
__device__ float  g_o[SEQ * 4096];

// round-to-nearest bf16 hi/lo split of a float4; low half of reg = even elem
__device__ __forceinline__ void split4(float4 f, uint32_t& h0, uint32_t& h1,
                                       uint32_t& l0, uint32_t& l1) {
    asm("cvt.rn.bf16x2.f32 %0, %1, %2;" : "=r"(h0) : "f"(f.y), "f"(f.x));
    asm("cvt.rn.bf16x2.f32 %0, %1, %2;" : "=r"(h1) : "f"(f.w), "f"(f.z));
    float hx = __uint_as_float(h0 << 16), hy = __uint_as_float(h0 & 0xFFFF0000u);
    float hz = __uint_as_float(h1 << 16), hw = __uint_as_float(h1 & 0xFFFF0000u);
    float lx = f.x - hx, ly = f.y - hy, lz = f.z - hz, lw = f.w - hw;
    asm("cvt.rn.bf16x2.f32 %0, %1, %2;" : "=r"(l0) : "f"(ly), "f"(lx));
    asm("cvt.rn.bf16x2.f32 %0, %1, %2;" : "=r"(l1) : "f"(lw), "f"(lz));
}

#define MMA16816(C, A0, A1, A2, A3, B0, B1)                                         \
    asm volatile(                                                                   \
        "mma.sync.aligned.m16n8k16.row.col.f32.bf16.bf16.f32 "                      \
        "{%0,%1,%2,%3},{%4,%5,%6,%7},{%8,%9},{%0,%1,%2,%3};"                        \
        : "+f"((C)[0]), "+f"((C)[1]), "+f"((C)[2]), "+f"((C)[3])                    \
        : "r"(A0), "r"(A1), "r"(A2), "r"(A3), "r"(B0), "r"(B1))

#define MMAH16816(C, A0, A1, A2, A3, B0, B1)                                        \
    asm volatile(                                                                   \
        "mma.sync.aligned.m16n8k16.row.col.f32.f16.f16.f32 "                        \
        "{%0,%1,%2,%3},{%4,%5,%6,%7},{%8,%9},{%0,%1,%2,%3};"                        \
        : "+f"((C)[0]), "+f"((C)[1]), "+f"((C)[2]), "+f"((C)[3])                    \
        : "r"(A0), "r"(A1), "r"(A2), "r"(A3), "r"(B0), "r"(B1))

#define LDSM4(R0, R1, R2, R3, ADDR)                                                 \
    asm volatile("ldmatrix.sync.aligned.m8n8.x4.shared.b16 {%0,%1,%2,%3},[%4];"     \
                 : "=r"(R0), "=r"(R1), "=r"(R2), "=r"(R3) : "r"(ADDR))

#define LDSM4T(R0, R1, R2, R3, ADDR)                                                \
    asm volatile("ldmatrix.sync.aligned.m8n8.x4.trans.shared.b16 {%0,%1,%2,%3},[%4];" \
                 : "=r"(R0), "=r"(R1), "=r"(R2), "=r"(R3) : "r"(ADDR))

#define STS64(ADDR, V0, V1)                                                         \
    asm volatile("st.shared.v2.b32 [%0],{%1,%2};" :: "r"(ADDR), "r"(V0), "r"(V1))
#define STS32(ADDR, V0)                                                             \
    asm volatile("st.shared.b32 [%0],%1;" :: "r"(ADDR), "r"(V0))
#define CP16(saddr, gptr)                                                           \
    asm volatile("cp.async.cg.shared.global [%0], [%1], 16;"                        \
                 :: "r"(saddr), "l"(gptr))
#define CP_COMMIT() asm volatile("cp.async.commit_group;" ::: "memory")

#define STG_BYTES 40960
#define ALO_OFF   10240u
#define BHI_OFF   20480u
#define BLO_OFF   30720u

// ======== generic bf16x3 GEMM (projections / WO). BM=BN=128, BK=32, 512 thr ====
template <bool ROPE, bool OUTH>
__global__ void __launch_bounds__(512, 1) gemm_k(
    const float* __restrict__ A, int lda,
    const float* __restrict__ B, int ldb,
    float* __restrict__ C, int ldc,
    int K, const float* __restrict__ cosp, const float* __restrict__ sinp)
{
    extern __shared__ char sh[];
    const int tid = threadIdx.x;
    const int lane = tid & 31, warp = tid >> 5;
    const int g = lane >> 2, t4 = lane & 3;
    const int wm = (warp & 3) * 32, wn = (warp >> 2) * 32;
    const int bm = blockIdx.y * 128, bn = blockIdx.x * 128;

    uint32_t sbase;
    asm("{ .reg .u64 t; cvta.to.shared.u64 t, %1; cvt.u32.u64 %0, t; }"
        : "=r"(sbase) : "l"(sh));

    const float* pA[2];
    const float* pB[2];
    uint32_t sA[2], sB[2];
#pragma unroll
    for (int j = 0; j < 2; j++) {
        int idx = tid + j * 512;
        int r = idx >> 3, c4 = idx & 7;
        pA[j] = A + (size_t)(bm + r) * lda + c4 * 4;
        sA[j] = sbase + (uint32_t)(r * 80 + c4 * 8);
        int kr = idx >> 5, n4 = idx & 31;
        pB[j] = B + (size_t)kr * ldb + bn + n4 * 4;
        sB[j] = sbase + BHI_OFF + (uint32_t)(kr * 272 + n4 * 8);
    }

    const int lr = (lane & 7) + ((lane >> 3) & 1) * 8;
    const int lk = lane >> 4;
    uint32_t aAddr[2], bAddr[2];
#pragma unroll
    for (int mi = 0; mi < 2; mi++)
        aAddr[mi] = sbase + (uint32_t)((wm + mi * 16 + lr) * 80 + lk * 16);
#pragma unroll
    for (int nb = 0; nb < 2; nb++) {
        int kk = (lane & 7) + lk * 8;
        int nc = (wn >> 3) + nb * 2 + ((lane >> 3) & 1);
        bAddr[nb] = sbase + BHI_OFF + (uint32_t)(kk * 272 + nc * 16);
    }

    float acc[2][4][4];
#pragma unroll
    for (int i = 0; i < 2; i++)
#pragma unroll
        for (int j = 0; j < 4; j++)
#pragma unroll
            for (int l = 0; l < 4; l++) acc[i][j][l] = 0.f;

    float4 ra[2], rb[2];
    auto ldg = [&]() {
#pragma unroll
        for (int j = 0; j < 2; j++) {
            ra[j] = *(const float4*)pA[j];
            rb[j] = *(const float4*)pB[j];
            pA[j] += 32;
            pB[j] += (size_t)32 * ldb;
        }
    };
    auto sts = [&](int st) {
        uint32_t so = (uint32_t)st * STG_BYTES;
#pragma unroll
        for (int j = 0; j < 2; j++) {
            uint32_t h0, h1, l0, l1;
            split4(ra[j], h0, h1, l0, l1);
            STS64(sA[j] + so, h0, h1);
            STS64(sA[j] + so + ALO_OFF, l0, l1);
            split4(rb[j], h0, h1, l0, l1);
            STS64(sB[j] + so, h0, h1);
            STS64(sB[j] + so + (BLO_OFF - BHI_OFF), l0, l1);
        }
    };

    const int nK = K >> 5;
    ldg();
    sts(0);
    __syncthreads();

    for (int t = 0; t < nK; t++) {
        const bool more = (t + 1 < nK);
        if (more) ldg();
        const uint32_t so = (uint32_t)(t & 1) * STG_BYTES;
#pragma unroll
        for (int kb = 0; kb < 2; kb++) {
            uint32_t AH[2][4], AL[2][4], BH[4][2], BL[4][2];
#pragma unroll
            for (int mi = 0; mi < 2; mi++) {
                uint32_t ad = aAddr[mi] + so + kb * 32;
                LDSM4(AH[mi][0], AH[mi][1], AH[mi][2], AH[mi][3], ad);
                LDSM4(AL[mi][0], AL[mi][1], AL[mi][2], AL[mi][3], ad + ALO_OFF);
            }
#pragma unroll
            for (int nb = 0; nb < 2; nb++) {
                uint32_t q0, q1, q2, q3;
                uint32_t bd = bAddr[nb] + so + kb * (16 * 272);
                LDSM4T(q0, q1, q2, q3, bd);
                BH[2 * nb][0] = q0; BH[2 * nb][1] = q2;
                BH[2 * nb + 1][0] = q1; BH[2 * nb + 1][1] = q3;
                LDSM4T(q0, q1, q2, q3, bd + (BLO_OFF - BHI_OFF));
                BL[2 * nb][0] = q0; BL[2 * nb][1] = q2;
                BL[2 * nb + 1][0] = q1; BL[2 * nb + 1][1] = q3;
            }
#pragma unroll
            for (int mi = 0; mi < 2; mi++)
#pragma unroll
                for (int ni = 0; ni < 4; ni++) {
                    MMA16816(acc[mi][ni], AH[mi][0], AH[mi][1], AH[mi][2], AH[mi][3],
                             BL[ni][0], BL[ni][1]);
                    MMA16816(acc[mi][ni], AL[mi][0], AL[mi][1], AL[mi][2], AL[mi][3],
                             BH[ni][0], BH[ni][1]);
                    MMA16816(acc[mi][ni], AH[mi][0], AH[mi][1], AH[mi][2], AH[mi][3],
                             BH[ni][0], BH[ni][1]);
                }
        }
        if (more) sts((t + 1) & 1);
        __syncthreads();
    }

#pragma unroll
    for (int mi = 0; mi < 2; mi++) {
        int rowg = bm + wm + mi * 16 + g;
#pragma unroll
        for (int ni = 0; ni < 4; ni++) {
            int colg = bn + wn + ni * 8 + 2 * t4;
            float c0 = acc[mi][ni][0], c1 = acc[mi][ni][1];
            float c2 = acc[mi][ni][2], c3 = acc[mi][ni][3];
            if (ROPE) {
                int i = (colg & 127) >> 1;
                float cs = cosp[rowg * 64 + i], sn = sinp[rowg * 64 + i];
                float cs2 = cosp[(rowg + 8) * 64 + i], sn2 = sinp[(rowg + 8) * 64 + i];
                float o0 = c0 * cs - c1 * sn, o1 = c0 * sn + c1 * cs;
                float o2 = c2 * cs2 - c3 * sn2, o3 = c2 * sn2 + c3 * cs2;
                c0 = o0; c1 = o1; c2 = o2; c3 = o3;
            }
            if (OUTH) {
                __half* Ch = (__half*)C;
                *(__half2*)(Ch + (size_t)rowg * ldc + colg) = __floats2half2_rn(c0, c1);
                *(__half2*)(Ch + (size_t)(rowg + 8) * ldc + colg) = __floats2half2_rn(c2, c3);
            } else {
                *(float2*)(C + (size_t)rowg * ldc + colg) = make_float2(c0, c1);
                *(float2*)(C + (size_t)(rowg + 8) * ldc + colg) = make_float2(c2, c3);
            }
        }
    }
}

// ======== flash attention: S=Q·Kᵀ, online softmax, O+=P·V, all fp16 operands ====
// block = (q-tile of 128 rows, head). 512 thr, warps 4(M)x4(N).
// smem: Q 0 (34816) | K 2 stages at 34816 (2x34816) | V 104448 (34816) |
//       P 139264 (34816) | red 174080 (4096)  => 178176 total. pitch 272B.
#define FK_K   34816u
#define FK_V   104448u
#define FK_P   139264u
#define FK_RED 174080u
#define FK_SM  178176

__global__ void __launch_bounds__(512, 1) flash_k(
    const __half* __restrict__ Qm, const __half* __restrict__ Km,
    const __half* __restrict__ Vm, float* __restrict__ Og, float scale)
{
    extern __shared__ char sh[];
    const int h = blockIdx.y;
    const int bm = blockIdx.x * 128;
    const int tid = threadIdx.x;
    const int lane = tid & 31, warp = tid >> 5;
    const int g = lane >> 2, t4 = lane & 3;
    const int wm = (warp & 3) * 32, wn = (warp >> 2) * 32;
    const int wN = warp >> 2;

    uint32_t sbase;
    asm("{ .reg .u64 t; cvta.to.shared.u64 t, %1; cvt.u32.u64 %0, t; }"
        : "=r"(sbase) : "l"(sh));
    float* redM = (float*)(sh + FK_RED);
    float* redS = redM + 512;

    const __half* Qg = Qm + (size_t)bm * 4096 + h * 128;
    const __half* Kg = Km + (size_t)(h >> 2) * 128;
    const __half* Vg = Vm + (size_t)(h >> 2) * 128;

    // Q tile (cp group 0)
#pragma unroll
    for (int j = 0; j < 4; j++) {
        int idx = tid + j * 512;
        int r = idx >> 4, c = idx & 15;
        CP16(sbase + (uint32_t)(r * 272 + c * 16), Qg + (size_t)r * 4096 + c * 8);
    }
    CP_COMMIT();

    auto cpK = [&](int t) {
        uint32_t dst = sbase + FK_K + (uint32_t)(t & 1) * 34816u;
        const __half* src = Kg + (size_t)t * 128 * 1024;
#pragma unroll
        for (int j = 0; j < 4; j++) {
            int idx = tid + j * 512;
            int r = idx >> 4, c = idx & 15;
            CP16(dst + (uint32_t)(r * 272 + c * 16), src + (size_t)r * 1024 + c * 8);
        }
        CP_COMMIT();
    };
    auto cpV = [&](int t) {
        uint32_t dst = sbase + FK_V;
        const __half* src = Vg + (size_t)t * 128 * 1024;
#pragma unroll
        for (int j = 0; j < 4; j++) {
            int idx = tid + j * 512;
            int r = idx >> 4, c = idx & 15;
            CP16(dst + (uint32_t)(r * 272 + c * 16), src + (size_t)r * 1024 + c * 8);
        }
        CP_COMMIT();
    };
    cpK(0);
    cpV(0);

    const int lr = (lane & 7) + ((lane >> 3) & 1) * 8;
    const int lk = lane >> 4;
    uint32_t qAddr[2], pAddr[2], kAddr[2], vAddr[2];
#pragma unroll
    for (int mi = 0; mi < 2; mi++) {
        qAddr[mi] = sbase + (uint32_t)((wm + mi * 16 + lr) * 272 + lk * 16);
        pAddr[mi] = sbase + FK_P + (uint32_t)((wm + mi * 16 + lr) * 272 + lk * 16);
    }
#pragma unroll
    for (int nb = 0; nb < 2; nb++) {
        kAddr[nb] = sbase + FK_K + (uint32_t)((wn + nb * 16 + lr) * 272 + lk * 16);
        vAddr[nb] = sbase + FK_V +
                    (uint32_t)(((lane & 7) + lk * 8) * 272 +
                               ((wn >> 3) + nb * 2 + ((lane >> 3) & 1)) * 16);
    }

    float accO[2][4][4];
#pragma unroll
    for (int i = 0; i < 2; i++)
#pragma unroll
        for (int j = 0; j < 4; j++)
#pragma unroll
            for (int l = 0; l < 4; l++) accO[i][j][l] = 0.f;
    float mrow[2][2] = {{-1e30f, -1e30f}, {-1e30f, -1e30f}};
    float lsum[2][2] = {{0.f, 0.f}, {0.f, 0.f}};

    for (int t = 0; t < 16; t++) {
        asm volatile("cp.async.wait_group 1;" ::: "memory");
        __syncthreads();

        // ---- S = Q K^T on tile t ----
        float accS[2][4][4];
#pragma unroll
        for (int i = 0; i < 2; i++)
#pragma unroll
            for (int j = 0; j < 4; j++)
#pragma unroll
                for (int l = 0; l < 4; l++) accS[i][j][l] = 0.f;
        const uint32_t kst = (uint32_t)(t & 1) * 34816u;
#pragma unroll
        for (int kk = 0; kk < 8; kk++) {
            uint32_t QA[2][4], KB[4][2];
#pragma unroll
            for (int mi = 0; mi < 2; mi++)
                LDSM4(QA[mi][0], QA[mi][1], QA[mi][2], QA[mi][3], qAddr[mi] + kk * 32);
#pragma unroll
            for (int nb = 0; nb < 2; nb++) {
                uint32_t q0, q1, q2, q3;
                LDSM4(q0, q1, q2, q3, kAddr[nb] + kst + kk * 32);
                KB[2 * nb][0] = q0; KB[2 * nb][1] = q2;
                KB[2 * nb + 1][0] = q1; KB[2 * nb + 1][1] = q3;
            }
#pragma unroll
            for (int mi = 0; mi < 2; mi++)
#pragma unroll
                for (int ni = 0; ni < 4; ni++)
                    MMAH16816(accS[mi][ni], QA[mi][0], QA[mi][1], QA[mi][2], QA[mi][3],
                              KB[ni][0], KB[ni][1]);
        }
        if (t < 15) cpK(t + 1);

        // ---- tile row max (scale folded here) ----
        float tm[2][2] = {{-1e30f, -1e30f}, {-1e30f, -1e30f}};
#pragma unroll
        for (int mi = 0; mi < 2; mi++)
#pragma unroll
            for (int ni = 0; ni < 4; ni++) {
                accS[mi][ni][0] *= scale; accS[mi][ni][1] *= scale;
                accS[mi][ni][2] *= scale; accS[mi][ni][3] *= scale;
                tm[mi][0] = fmaxf(tm[mi][0], fmaxf(accS[mi][ni][0], accS[mi][ni][1]));
                tm[mi][1] = fmaxf(tm[mi][1], fmaxf(accS[mi][ni][2], accS[mi][ni][3]));
            }
#pragma unroll
        for (int mi = 0; mi < 2; mi++)
#pragma unroll
            for (int hh = 0; hh < 2; hh++) {
                tm[mi][hh] = fmaxf(tm[mi][hh], __shfl_xor_sync(0xffffffffu, tm[mi][hh], 1));
                tm[mi][hh] = fmaxf(tm[mi][hh], __shfl_xor_sync(0xffffffffu, tm[mi][hh], 2));
            }
        if (t4 == 0)
#pragma unroll
            for (int mi = 0; mi < 2; mi++)
#pragma unroll
                for (int hh = 0; hh < 2; hh++)
                    redM[wN * 128 + wm + mi * 16 + g + hh * 8] = tm[mi][hh];
        __syncthreads();

        float Mn[2][2], al[2][2];
#pragma unroll
        for (int mi = 0; mi < 2; mi++)
#pragma unroll
            for (int hh = 0; hh < 2; hh++) {
                int row = wm + mi * 16 + g + hh * 8;
                float m = fmaxf(fmaxf(redM[row], redM[128 + row]),
                                fmaxf(redM[256 + row], redM[384 + row]));
                Mn[mi][hh] = fmaxf(mrow[mi][hh], m);
                al[mi][hh] = __expf(mrow[mi][hh] - Mn[mi][hh]);
                mrow[mi][hh] = Mn[mi][hh];
            }

        // ---- P = exp(S - M) -> fp16 smem; partial row sums ----
        float rs[2][2] = {{0.f, 0.f}, {0.f, 0.f}};
#pragma unroll
        for (int mi = 0; mi < 2; mi++)
#pragma unroll
            for (int ni = 0; ni < 4; ni++) {
                float p0 = __expf(accS[mi][ni][0] - Mn[mi][0]);
                float p1 = __expf(accS[mi][ni][1] - Mn[mi][0]);
                float p2 = __expf(accS[mi][ni][2] - Mn[mi][1]);
                float p3 = __expf(accS[mi][ni][3] - Mn[mi][1]);
                rs[mi][0] += p0 + p1;
                rs[mi][1] += p2 + p3;
                __half2 hA = __floats2half2_rn(p0, p1);
                __half2 hB = __floats2half2_rn(p2, p3);
                uint32_t a0 = sbase + FK_P +
                              (uint32_t)((wm + mi * 16 + g) * 272 +
                                         (wn + ni * 8 + 2 * t4) * 2);
                STS32(a0, *(uint32_t*)&hA);
                STS32(a0 + 8 * 272, *(uint32_t*)&hB);
            }
#pragma unroll
        for (int mi = 0; mi < 2; mi++)
#pragma unroll
            for (int hh = 0; hh < 2; hh++) {
                rs[mi][hh] += __shfl_xor_sync(0xffffffffu, rs[mi][hh], 1);
                rs[mi][hh] += __shfl_xor_sync(0xffffffffu, rs[mi][hh], 2);
            }
        if (t4 == 0)
#pragma unroll
            for (int mi = 0; mi < 2; mi++)
#pragma unroll
                for (int hh = 0; hh < 2; hh++)
                    redS[wN * 128 + wm + mi * 16 + g + hh * 8] = rs[mi][hh];
        if (t < 15) asm volatile("cp.async.wait_group 1;" ::: "memory");
        else        asm volatile("cp.async.wait_group 0;" ::: "memory");
        __syncthreads();

#pragma unroll
        for (int mi = 0; mi < 2; mi++)
#pragma unroll
            for (int hh = 0; hh < 2; hh++) {
                int row = wm + mi * 16 + g + hh * 8;
                float rsum = redS[row] + redS[128 + row] + redS[256 + row] + redS[384 + row];
                lsum[mi][hh] = lsum[mi][hh] * al[mi][hh] + rsum;
            }
#pragma unroll
        for (int mi = 0; mi < 2; mi++)
#pragma unroll
            for (int ni = 0; ni < 4; ni++) {
                accO[mi][ni][0] *= al[mi][0]; accO[mi][ni][1] *= al[mi][0];
                accO[mi][ni][2] *= al[mi][1]; accO[mi][ni][3] *= al[mi][1];
            }

        // ---- O += P V ----
#pragma unroll
        for (int kk = 0; kk < 8; kk++) {
            uint32_t PA[2][4], VB[4][2];
#pragma unroll
            for (int mi = 0; mi < 2; mi++)
                LDSM4(PA[mi][0], PA[mi][1], PA[mi][2], PA[mi][3], pAddr[mi] + kk * 32);
#pragma unroll
            for (int nb = 0; nb < 2; nb++) {
                uint32_t q0, q1, q2, q3;
                LDSM4T(q0, q1, q2, q3, vAddr[nb] + kk * (16 * 272));
                VB[2 * nb][0] = q0; VB[2 * nb][1] = q2;
                VB[2 * nb + 1][0] = q1; VB[2 * nb + 1][1] = q3;
            }
#pragma unroll
            for (int mi = 0; mi < 2; mi++)
#pragma unroll
                for (int ni = 0; ni < 4; ni++)
                    MMAH16816(accO[mi][ni], PA[mi][0], PA[mi][1], PA[mi][2], PA[mi][3],
                              VB[ni][0], VB[ni][1]);
        }
        __syncthreads();
        if (t < 15) cpV(t + 1);
    }

    // ---- epilogue: O / l -> gmem fp32 ----
    float inv[2][2];
#pragma unroll
    for (int mi = 0; mi < 2; mi++)
#pragma unroll
        for (int hh = 0; hh < 2; hh++) inv[mi][hh] = 1.0f / lsum[mi][hh];
#pragma unroll
    for (int mi = 0; mi < 2; mi++) {
        int rowg = bm + wm + mi * 16 + g;
#pragma unroll
        for (int ni = 0; ni < 4; ni++) {
            int colg = h * 128 + wn + ni * 8 + 2 * t4;
            *(float2*)(Og + (size_t)rowg * 4096 + colg) =
                make_float2(accO[mi][ni][0] * inv[mi][0], accO[mi][ni][1] * inv[mi][0]);
            *(float2*)(Og + (size_t)(rowg + 8) * 4096 + colg) =
                make_float2(accO[mi][ni][2] * inv[mi][1], accO[mi][ni][3] * inv[mi][1]);
        }
    }
}

extern "C" void kernel_launch(void* const* d_in, const int* in_sizes, int n_in,
                              void* d_out, int out_size) {
    const float* x  = (const float*)d_in[0];
    const float* fc = (const float*)d_in[1];
    const float* fs = (const float*)d_in[2];
    const float* wq = (const float*)d_in[3];
    const float* wk = (const float*)d_in[4];
    const float* wv = (const float*)d_in[5];
    const float* wo = (const float*)d_in[6];
    float* out = (float*)d_out;

    __half *qh, *kh, *vh;
    float* o;
    cudaGetSymbolAddress((void**)&qh, g_qh);
    cudaGetSymbolAddress((void**)&kh, g_kh);
    cudaGetSymbolAddress((void**)&vh, g_vh);
    cudaGetSymbolAddress((void**)&o,  g_o);

    const int SM = 2 * STG_BYTES;  // 81920
    cudaFuncSetAttribute(gemm_k<true,  true >, cudaFuncAttributeMaxDynamicSharedMemorySize, SM);
    cudaFuncSetAttribute(gemm_k<false, true >, cudaFuncAttributeMaxDynamicSharedMemorySize, SM);
    cudaFuncSetAttribute(gemm_k<false, false>, cudaFuncAttributeMaxDynamicSharedMemorySize, SM);
    cudaFuncSetAttribute(flash_k, cudaFuncAttributeMaxDynamicSharedMemorySize, FK_SM);

    const dim3 blk(512);
    const float scale = 0.08838834764831845f;  // 1/sqrt(128)

    gemm_k<true,  true ><<<dim3(32, 16), blk, SM>>>(x, 4096, wq, 4096, (float*)qh, 4096, 4096, fc, fs);
    gemm_k<true,  true ><<<dim3( 8, 16), blk, SM>>>(x, 4096, wk, 1024, (float*)kh, 1024, 4096, fc, fs);
    gemm_k<false, true ><<<dim3( 8, 16), blk, SM>>>(x, 4096, wv, 1024, (float*)vh, 1024, 4096, nullptr, nullptr);
    flash_k<<<dim3(16, NHEADS), blk, FK_SM>>>(qh, kh, vh, o, scale);
    gemm_k<false, false><<<dim3(32, 16), blk, SM>>>(o, 4096, wo, 4096, out, 4096, 4096, nullptr, nullptr);
}

// round 11
// speedup vs baseline: 2.7865x; 1.1650x over previous
#include <cuda_runtime.h>
#include <cuda_fp16.h>
#include <cstdint>
#include <cstddef>

#define SEQ 2048
#define NHEADS 32

__device__ __half g_qh[SEQ * 4096];
__device__ __half g_kh[SEQ * 1024];
__device__ __half g_vh[SEQ * 1024];
__device__ float  g_o[SEQ * 4096];

// fp16 hi/lo split of a float4 (B/weight path; near-exact 2-term split)
__device__ __forceinline__ void splitH4(float4 f, uint32_t& h0, uint32_t& h1,
                                        uint32_t& l0, uint32_t& l1) {
    __half2 a = __floats2half2_rn(f.x, f.y);
    __half2 b = __floats2half2_rn(f.z, f.w);
    float2 af = __half22float2(a), bf = __half22float2(b);
    __half2 c = __floats2half2_rn(f.x - af.x, f.y - af.y);
    __half2 d = __floats2half2_rn(f.z - bf.x, f.w - bf.y);
    h0 = *(uint32_t*)&a; h1 = *(uint32_t*)&b;
    l0 = *(uint32_t*)&c; l1 = *(uint32_t*)&d;
}

#define MMAH16816(C, A0, A1, A2, A3, B0, B1)                                        \
    asm volatile(                                                                   \
        "mma.sync.aligned.m16n8k16.row.col.f32.f16.f16.f32 "                        \
        "{%0,%1,%2,%3},{%4,%5,%6,%7},{%8,%9},{%0,%1,%2,%3};"                        \
        : "+f"((C)[0]), "+f"((C)[1]), "+f"((C)[2]), "+f"((C)[3])                    \
        : "r"(A0), "r"(A1), "r"(A2), "r"(A3), "r"(B0), "r"(B1))
#define LDSM4(R0, R1, R2, R3, ADDR)                                                 \
    asm volatile("ldmatrix.sync.aligned.m8n8.x4.shared.b16 {%0,%1,%2,%3},[%4];"     \
                 : "=r"(R0), "=r"(R1), "=r"(R2), "=r"(R3) : "r"(ADDR))
#define LDSM4T(R0, R1, R2, R3, ADDR)                                                \
    asm volatile("ldmatrix.sync.aligned.m8n8.x4.trans.shared.b16 {%0,%1,%2,%3},[%4];" \
                 : "=r"(R0), "=r"(R1), "=r"(R2), "=r"(R3) : "r"(ADDR))
#define STS64(ADDR, V0, V1)                                                         \
    asm volatile("st.shared.v2.b32 [%0],{%1,%2};" :: "r"(ADDR), "r"(V0), "r"(V1))
#define STS32(ADDR, V0) asm volatile("st.shared.b32 [%0],%1;" :: "r"(ADDR), "r"(V0))
#define CP16(saddr, gptr)                                                           \
    asm volatile("cp.async.cg.shared.global [%0], [%1], 16;" :: "r"(saddr), "l"(gptr))
#define CP_COMMIT() asm volatile("cp.async.commit_group;" ::: "memory")

// ======== fp16x2 GEMM: C[2048 x N] = round16(A[2048 x K]) * splitH(B[K x N]) ====
// BM=BN=128, BK=32, 512 threads, warps 4(M)x4(N), warp tile 32x32.
// smem/stage: A(fp16) 0..10240 pitch 80 | Bh 10240..18944 pitch 272 | Bl 18944..27648
#define H2_STG 27648
#define H2_BH  10240u
#define H2_BL  18944u

template <bool ROPE, bool OUTH>
__global__ void __launch_bounds__(512, 1) gemm_h2(
    const float* __restrict__ A, int lda,
    const float* __restrict__ B, int ldb,
    void* __restrict__ Cout, int ldc,
    int K, const float* __restrict__ cosp, const float* __restrict__ sinp)
{
    extern __shared__ char sh[];
    const int tid = threadIdx.x;
    const int lane = tid & 31, warp = tid >> 5;
    const int g = lane >> 2, t4 = lane & 3;
    const int wm = (warp & 3) * 32, wn = (warp >> 2) * 32;
    const int bm = blockIdx.y * 128, bn = blockIdx.x * 128;

    uint32_t sbase;
    asm("{ .reg .u64 t; cvta.to.shared.u64 t, %1; cvt.u32.u64 %0, t; }"
        : "=r"(sbase) : "l"(sh));

    const float* pA[2];
    const float* pB[2];
    uint32_t sA[2], sB[2];
#pragma unroll
    for (int j = 0; j < 2; j++) {
        int idx = tid + j * 512;
        int r = idx >> 3, c4 = idx & 7;            // A: row r, f4-chunk c4
        pA[j] = A + (size_t)(bm + r) * lda + c4 * 4;
        sA[j] = sbase + (uint32_t)(r * 80 + c4 * 8);
        int kr = idx >> 5, n4 = idx & 31;          // B: k-row kr, n-f4 n4
        pB[j] = B + (size_t)kr * ldb + bn + n4 * 4;
        sB[j] = sbase + H2_BH + (uint32_t)(kr * 272 + n4 * 8);
    }

    const int lr = (lane & 7) + ((lane >> 3) & 1) * 8;
    const int lk = lane >> 4;
    uint32_t aAddr[2], bAddr[2];
#pragma unroll
    for (int mi = 0; mi < 2; mi++)
        aAddr[mi] = sbase + (uint32_t)((wm + mi * 16 + lr) * 80 + lk * 16);
#pragma unroll
    for (int nb = 0; nb < 2; nb++) {
        int kk = (lane & 7) + lk * 8;
        int nc = (wn >> 3) + nb * 2 + ((lane >> 3) & 1);
        bAddr[nb] = sbase + H2_BH + (uint32_t)(kk * 272 + nc * 16);
    }

    float acc[2][4][4];
#pragma unroll
    for (int i = 0; i < 2; i++)
#pragma unroll
        for (int j = 0; j < 4; j++)
#pragma unroll
            for (int l = 0; l < 4; l++) acc[i][j][l] = 0.f;

    float4 ra[2], rb[2];
    auto ldg = [&]() {
#pragma unroll
        for (int j = 0; j < 2; j++) {
            ra[j] = *(const float4*)pA[j];
            rb[j] = *(const float4*)pB[j];
            pA[j] += 32;
            pB[j] += (size_t)32 * ldb;
        }
    };
    auto sts = [&](int st) {
        uint32_t so = (uint32_t)st * H2_STG;
#pragma unroll
        for (int j = 0; j < 2; j++) {
            __half2 a0 = __floats2half2_rn(ra[j].x, ra[j].y);
            __half2 a1 = __floats2half2_rn(ra[j].z, ra[j].w);
            STS64(sA[j] + so, *(uint32_t*)&a0, *(uint32_t*)&a1);
            uint32_t h0, h1, l0, l1;
            splitH4(rb[j], h0, h1, l0, l1);
            STS64(sB[j] + so, h0, h1);
            STS64(sB[j] + so + (H2_BL - H2_BH), l0, l1);
        }
    };

    const int nK = K >> 5;
    ldg();
    sts(0);
    __syncthreads();

    for (int t = 0; t < nK; t++) {
        const bool more = (t + 1 < nK);
        if (more) ldg();
        const uint32_t so = (uint32_t)(t & 1) * H2_STG;
#pragma unroll
        for (int kb = 0; kb < 2; kb++) {
            uint32_t AH[2][4], BH[4][2], BL[4][2];
#pragma unroll
            for (int mi = 0; mi < 2; mi++)
                LDSM4(AH[mi][0], AH[mi][1], AH[mi][2], AH[mi][3],
                      aAddr[mi] + so + kb * 32);
#pragma unroll
            for (int nb = 0; nb < 2; nb++) {
                uint32_t q0, q1, q2, q3;
                uint32_t bd = bAddr[nb] + so + kb * (16 * 272);
                LDSM4T(q0, q1, q2, q3, bd);
                BH[2 * nb][0] = q0; BH[2 * nb][1] = q2;
                BH[2 * nb + 1][0] = q1; BH[2 * nb + 1][1] = q3;
                LDSM4T(q0, q1, q2, q3, bd + (H2_BL - H2_BH));
                BL[2 * nb][0] = q0; BL[2 * nb][1] = q2;
                BL[2 * nb + 1][0] = q1; BL[2 * nb + 1][1] = q3;
            }
#pragma unroll
            for (int mi = 0; mi < 2; mi++)
#pragma unroll
                for (int ni = 0; ni < 4; ni++) {
                    MMAH16816(acc[mi][ni], AH[mi][0], AH[mi][1], AH[mi][2], AH[mi][3],
                              BL[ni][0], BL[ni][1]);
                    MMAH16816(acc[mi][ni], AH[mi][0], AH[mi][1], AH[mi][2], AH[mi][3],
                              BH[ni][0], BH[ni][1]);
                }
        }
        if (more) sts((t + 1) & 1);
        __syncthreads();
    }

#pragma unroll
    for (int mi = 0; mi < 2; mi++) {
        int rowg = bm + wm + mi * 16 + g;
#pragma unroll
        for (int ni = 0; ni < 4; ni++) {
            int colg = bn + wn + ni * 8 + 2 * t4;
            float c0 = acc[mi][ni][0], c1 = acc[mi][ni][1];
            float c2 = acc[mi][ni][2], c3 = acc[mi][ni][3];
            if (ROPE) {
                int i = (colg & 127) >> 1;
                float cs = cosp[rowg * 64 + i], sn = sinp[rowg * 64 + i];
                float cs2 = cosp[(rowg + 8) * 64 + i], sn2 = sinp[(rowg + 8) * 64 + i];
                float o0 = c0 * cs - c1 * sn, o1 = c0 * sn + c1 * cs;
                float o2 = c2 * cs2 - c3 * sn2, o3 = c2 * sn2 + c3 * cs2;
                c0 = o0; c1 = o1; c2 = o2; c3 = o3;
            }
            if (OUTH) {
                __half* Ch = (__half*)Cout;
                *(__half2*)(Ch + (size_t)rowg * ldc + colg) = __floats2half2_rn(c0, c1);
                *(__half2*)(Ch + (size_t)(rowg + 8) * ldc + colg) = __floats2half2_rn(c2, c3);
            } else {
                float* Cf = (float*)Cout;
                *(float2*)(Cf + (size_t)rowg * ldc + colg) = make_float2(c0, c1);
                *(float2*)(Cf + (size_t)(rowg + 8) * ldc + colg) = make_float2(c2, c3);
            }
        }
    }
}

// ======== flash attention (unchanged from R9 passing version) ========
#define FK_K   34816u
#define FK_V   104448u
#define FK_P   139264u
#define FK_RED 174080u
#define FK_SM  178176

__global__ void __launch_bounds__(512, 1) flash_k(
    const __half* __restrict__ Qm, const __half* __restrict__ Km,
    const __half* __restrict__ Vm, float* __restrict__ Og, float scale)
{
    extern __shared__ char sh[];
    const int h = blockIdx.y;
    const int bm = blockIdx.x * 128;
    const int tid = threadIdx.x;
    const int lane = tid & 31, warp = tid >> 5;
    const int g = lane >> 2, t4 = lane & 3;
    const int wm = (warp & 3) * 32, wn = (warp >> 2) * 32;
    const int wN = warp >> 2;

    uint32_t sbase;
    asm("{ .reg .u64 t; cvta.to.shared.u64 t, %1; cvt.u32.u64 %0, t; }"
        : "=r"(sbase) : "l"(sh));
    float* redM = (float*)(sh + FK_RED);
    float* redS = redM + 512;

    const __half* Qg = Qm + (size_t)bm * 4096 + h * 128;
    const __half* Kg = Km + (size_t)(h >> 2) * 128;
    const __half* Vg = Vm + (size_t)(h >> 2) * 128;

#pragma unroll
    for (int j = 0; j < 4; j++) {
        int idx = tid + j * 512;
        int r = idx >> 4, c = idx & 15;
        CP16(sbase + (uint32_t)(r * 272 + c * 16), Qg + (size_t)r * 4096 + c * 8);
    }
    CP_COMMIT();

    auto cpK = [&](int t) {
        uint32_t dst = sbase + FK_K + (uint32_t)(t & 1) * 34816u;
        const __half* src = Kg + (size_t)t * 128 * 1024;
#pragma unroll
        for (int j = 0; j < 4; j++) {
            int idx = tid + j * 512;
            int r = idx >> 4, c = idx & 15;
            CP16(dst + (uint32_t)(r * 272 + c * 16), src + (size_t)r * 1024 + c * 8);
        }
        CP_COMMIT();
    };
    auto cpV = [&](int t) {
        uint32_t dst = sbase + FK_V;
        const __half* src = Vg + (size_t)t * 128 * 1024;
#pragma unroll
        for (int j = 0; j < 4; j++) {
            int idx = tid + j * 512;
            int r = idx >> 4, c = idx & 15;
            CP16(dst + (uint32_t)(r * 272 + c * 16), src + (size_t)r * 1024 + c * 8);
        }
        CP_COMMIT();
    };
    cpK(0);
    cpV(0);

    const int lr = (lane & 7) + ((lane >> 3) & 1) * 8;
    const int lk = lane >> 4;
    uint32_t qAddr[2], pAddr[2], kAddr[2], vAddr[2];
#pragma unroll
    for (int mi = 0; mi < 2; mi++) {
        qAddr[mi] = sbase + (uint32_t)((wm + mi * 16 + lr) * 272 + lk * 16);
        pAddr[mi] = sbase + FK_P + (uint32_t)((wm + mi * 16 + lr) * 272 + lk * 16);
    }
#pragma unroll
    for (int nb = 0; nb < 2; nb++) {
        kAddr[nb] = sbase + FK_K + (uint32_t)((wn + nb * 16 + lr) * 272 + lk * 16);
        vAddr[nb] = sbase + FK_V +
                    (uint32_t)(((lane & 7) + lk * 8) * 272 +
                               ((wn >> 3) + nb * 2 + ((lane >> 3) & 1)) * 16);
    }

    float accO[2][4][4];
#pragma unroll
    for (int i = 0; i < 2; i++)
#pragma unroll
        for (int j = 0; j < 4; j++)
#pragma unroll
            for (int l = 0; l < 4; l++) accO[i][j][l] = 0.f;
    float mrow[2][2] = {{-1e30f, -1e30f}, {-1e30f, -1e30f}};
    float lsum[2][2] = {{0.f, 0.f}, {0.f, 0.f}};

    for (int t = 0; t < 16; t++) {
        asm volatile("cp.async.wait_group 1;" ::: "memory");
        __syncthreads();

        float accS[2][4][4];
#pragma unroll
        for (int i = 0; i < 2; i++)
#pragma unroll
            for (int j = 0; j < 4; j++)
#pragma unroll
                for (int l = 0; l < 4; l++) accS[i][j][l] = 0.f;
        const uint32_t kst = (uint32_t)(t & 1) * 34816u;
#pragma unroll
        for (int kk = 0; kk < 8; kk++) {
            uint32_t QA[2][4], KB[4][2];
#pragma unroll
            for (int mi = 0; mi < 2; mi++)
                LDSM4(QA[mi][0], QA[mi][1], QA[mi][2], QA[mi][3], qAddr[mi] + kk * 32);
#pragma unroll
            for (int nb = 0; nb < 2; nb++) {
                uint32_t q0, q1, q2, q3;
                LDSM4(q0, q1, q2, q3, kAddr[nb] + kst + kk * 32);
                KB[2 * nb][0] = q0; KB[2 * nb][1] = q2;
                KB[2 * nb + 1][0] = q1; KB[2 * nb + 1][1] = q3;
            }
#pragma unroll
            for (int mi = 0; mi < 2; mi++)
#pragma unroll
                for (int ni = 0; ni < 4; ni++)
                    MMAH16816(accS[mi][ni], QA[mi][0], QA[mi][1], QA[mi][2], QA[mi][3],
                              KB[ni][0], KB[ni][1]);
        }
        if (t < 15) cpK(t + 1);

        float tm[2][2] = {{-1e30f, -1e30f}, {-1e30f, -1e30f}};
#pragma unroll
        for (int mi = 0; mi < 2; mi++)
#pragma unroll
            for (int ni = 0; ni < 4; ni++) {
                accS[mi][ni][0] *= scale; accS[mi][ni][1] *= scale;
                accS[mi][ni][2] *= scale; accS[mi][ni][3] *= scale;
                tm[mi][0] = fmaxf(tm[mi][0], fmaxf(accS[mi][ni][0], accS[mi][ni][1]));
                tm[mi][1] = fmaxf(tm[mi][1], fmaxf(accS[mi][ni][2], accS[mi][ni][3]));
            }
#pragma unroll
        for (int mi = 0; mi < 2; mi++)
#pragma unroll
            for (int hh = 0; hh < 2; hh++) {
                tm[mi][hh] = fmaxf(tm[mi][hh], __shfl_xor_sync(0xffffffffu, tm[mi][hh], 1));
                tm[mi][hh] = fmaxf(tm[mi][hh], __shfl_xor_sync(0xffffffffu, tm[mi][hh], 2));
            }
        if (t4 == 0)
#pragma unroll
            for (int mi = 0; mi < 2; mi++)
#pragma unroll
                for (int hh = 0; hh < 2; hh++)
                    redM[wN * 128 + wm + mi * 16 + g + hh * 8] = tm[mi][hh];
        __syncthreads();

        float Mn[2][2], al[2][2];
#pragma unroll
        for (int mi = 0; mi < 2; mi++)
#pragma unroll
            for (int hh = 0; hh < 2; hh++) {
                int row = wm + mi * 16 + g + hh * 8;
                float m = fmaxf(fmaxf(redM[row], redM[128 + row]),
                                fmaxf(redM[256 + row], redM[384 + row]));
                Mn[mi][hh] = fmaxf(mrow[mi][hh], m);
                al[mi][hh] = __expf(mrow[mi][hh] - Mn[mi][hh]);
                mrow[mi][hh] = Mn[mi][hh];
            }

        float rs[2][2] = {{0.f, 0.f}, {0.f, 0.f}};
#pragma unroll
        for (int mi = 0; mi < 2; mi++)
#pragma unroll
            for (int ni = 0; ni < 4; ni++) {
                float p0 = __expf(accS[mi][ni][0] - Mn[mi][0]);
                float p1 = __expf(accS[mi][ni][1] - Mn[mi][0]);
                float p2 = __expf(accS[mi][ni][2] - Mn[mi][1]);
                float p3 = __expf(accS[mi][ni][3] - Mn[mi][1]);
                rs[mi][0] += p0 + p1;
                rs[mi][1] += p2 + p3;
                __half2 hA = __floats2half2_rn(p0, p1);
                __half2 hB = __floats2half2_rn(p2, p3);
                uint32_t a0 = sbase + FK_P +
                              (uint32_t)((wm + mi * 16 + g) * 272 + (wn + ni * 8 + 2 * t4) * 2);
                STS32(a0, *(uint32_t*)&hA);
                STS32(a0 + 8 * 272, *(uint32_t*)&hB);
            }
#pragma unroll
        for (int mi = 0; mi < 2; mi++)
#pragma unroll
            for (int hh = 0; hh < 2; hh++) {
                rs[mi][hh] += __shfl_xor_sync(0xffffffffu, rs[mi][hh], 1);
                rs[mi][hh] += __shfl_xor_sync(0xffffffffu, rs[mi][hh], 2);
            }
        if (t4 == 0)
#pragma unroll
            for (int mi = 0; mi < 2; mi++)
#pragma unroll
                for (int hh = 0; hh < 2; hh++)
                    redS[wN * 128 + wm + mi * 16 + g + hh * 8] = rs[mi][hh];
        if (t < 15) asm volatile("cp.async.wait_group 1;" ::: "memory");
        else        asm volatile("cp.async.wait_group 0;" ::: "memory");
        __syncthreads();

#pragma unroll
        for (int mi = 0; mi < 2; mi++)
#pragma unroll
            for (int hh = 0; hh < 2; hh++) {
                int row = wm + mi * 16 + g + hh * 8;
                float rsum = redS[row] + redS[128 + row] + redS[256 + row] + redS[384 + row];
                lsum[mi][hh] = lsum[mi][hh] * al[mi][hh] + rsum;
            }
#pragma unroll
        for (int mi = 0; mi < 2; mi++)
#pragma unroll
            for (int ni = 0; ni < 4; ni++) {
                accO[mi][ni][0] *= al[mi][0]; accO[mi][ni][1] *= al[mi][0];
                accO[mi][ni][2] *= al[mi][1]; accO[mi][ni][3] *= al[mi][1];
            }

#pragma unroll
        for (int kk = 0; kk < 8; kk++) {
            uint32_t PA[2][4], VB[4][2];
#pragma unroll
            for (int mi = 0; mi < 2; mi++)
                LDSM4(PA[mi][0], PA[mi][1], PA[mi][2], PA[mi][3], pAddr[mi] + kk * 32);
#pragma unroll
            for (int nb = 0; nb < 2; nb++) {
                uint32_t q0, q1, q2, q3;
                LDSM4T(q0, q1, q2, q3, vAddr[nb] + kk * (16 * 272));
                VB[2 * nb][0] = q0; VB[2 * nb][1] = q2;
                VB[2 * nb + 1][0] = q1; VB[2 * nb + 1][1] = q3;
            }
#pragma unroll
            for (int mi = 0; mi < 2; mi++)
#pragma unroll
                for (int ni = 0; ni < 4; ni++)
                    MMAH16816(accO[mi][ni], PA[mi][0], PA[mi][1], PA[mi][2], PA[mi][3],
                              VB[ni][0], VB[ni][1]);
        }
        __syncthreads();
        if (t < 15) cpV(t + 1);
    }

    float inv[2][2];
#pragma unroll
    for (int mi = 0; mi < 2; mi++)
#pragma unroll
        for (int hh = 0; hh < 2; hh++) inv[mi][hh] = 1.0f / lsum[mi][hh];
#pragma unroll
    for (int mi = 0; mi < 2; mi++) {
        int rowg = bm + wm + mi * 16 + g;
#pragma unroll
        for (int ni = 0; ni < 4; ni++) {
            int colg = h * 128 + wn + ni * 8 + 2 * t4;
            *(float2*)(Og + (size_t)rowg * 4096 + colg) =
                make_float2(accO[mi][ni][0] * inv[mi][0], accO[mi][ni][1] * inv[mi][0]);
            *(float2*)(Og + (size_t)(rowg + 8) * 4096 + colg) =
                make_float2(accO[mi][ni][2] * inv[mi][1], accO[mi][ni][3] * inv[mi][1]);
        }
    }
}

extern "C" void kernel_launch(void* const* d_in, const int* in_sizes, int n_in,
                              void* d_out, int out_size) {
    const float* x  = (const float*)d_in[0];
    const float* fc = (const float*)d_in[1];
    const float* fs = (const float*)d_in[2];
    const float* wq = (const float*)d_in[3];
    const float* wk = (const float*)d_in[4];
    const float* wv = (const float*)d_in[5];
    const float* wo = (const float*)d_in[6];
    float* out = (float*)d_out;

    __half *qh, *kh, *vh;
    float* o;
    cudaGetSymbolAddress((void**)&qh, g_qh);
    cudaGetSymbolAddress((void**)&kh, g_kh);
    cudaGetSymbolAddress((void**)&vh, g_vh);
    cudaGetSymbolAddress((void**)&o,  g_o);

    const int SM = 2 * H2_STG;  // 55296
    cudaFuncSetAttribute(gemm_h2<true,  true >, cudaFuncAttributeMaxDynamicSharedMemorySize, SM);
    cudaFuncSetAttribute(gemm_h2<false, true >, cudaFuncAttributeMaxDynamicSharedMemorySize, SM);
    cudaFuncSetAttribute(gemm_h2<false, false>, cudaFuncAttributeMaxDynamicSharedMemorySize, SM);
    cudaFuncSetAttribute(flash_k, cudaFuncAttributeMaxDynamicSharedMemorySize, FK_SM);

    const dim3 blk(512);
    const float scale = 0.08838834764831845f;  // 1/sqrt(128)

    gemm_h2<true,  true ><<<dim3(32, 16), blk, SM>>>(x, 4096, wq, 4096, qh, 4096, 4096, fc, fs);
    gemm_h2<true,  true ><<<dim3( 8, 16), blk, SM>>>(x, 4096, wk, 1024, kh, 1024, 4096, fc, fs);
    gemm_h2<false, true ><<<dim3( 8, 16), blk, SM>>>(x, 4096, wv, 1024, vh, 1024, 4096, nullptr, nullptr);
    flash_k<<<dim3(16, NHEADS), blk, FK_SM>>>(qh, kh, vh, o, scale);
    gemm_h2<false, false><<<dim3(32, 16), blk, SM>>>(o, 4096, wo, 4096, out, 4096, 4096, nullptr, nullptr);
}

// round 12
// speedup vs baseline: 2.8966x; 1.0395x over previous
#include <cuda_runtime.h>
#include <cuda_fp16.h>
#include <cstdint>
#include <cstddef>

#define SEQ 2048
#define NHEADS 32

__device__ __half g_qh[SEQ * 4096];
__device__ __half g_kh[SEQ * 1024];
__device__ __half g_vh[SEQ * 1024];
__device__ float  g_o[SEQ * 4096];

// fp16 hi/lo split of a float4 (weight path; near-exact 2-term split)
__device__ __forceinline__ void splitH4(float4 f, uint32_t& h0, uint32_t& h1,
                                        uint32_t& l0, uint32_t& l1) {
    __half2 a = __floats2half2_rn(f.x, f.y);
    __half2 b = __floats2half2_rn(f.z, f.w);
    float2 af = __half22float2(a), bf = __half22float2(b);
    __half2 c = __floats2half2_rn(f.x - af.x, f.y - af.y);
    __half2 d = __floats2half2_rn(f.z - bf.x, f.w - bf.y);
    h0 = *(uint32_t*)&a; h1 = *(uint32_t*)&b;
    l0 = *(uint32_t*)&c; l1 = *(uint32_t*)&d;
}

#define MMAH16816(C, A0, A1, A2, A3, B0, B1)                                        \
    asm volatile(                                                                   \
        "mma.sync.aligned.m16n8k16.row.col.f32.f16.f16.f32 "                        \
        "{%0,%1,%2,%3},{%4,%5,%6,%7},{%8,%9},{%0,%1,%2,%3};"                        \
        : "+f"((C)[0]), "+f"((C)[1]), "+f"((C)[2]), "+f"((C)[3])                    \
        : "r"(A0), "r"(A1), "r"(A2), "r"(A3), "r"(B0), "r"(B1))
#define LDSM4(R0, R1, R2, R3, ADDR)                                                 \
    asm volatile("ldmatrix.sync.aligned.m8n8.x4.shared.b16 {%0,%1,%2,%3},[%4];"     \
                 : "=r"(R0), "=r"(R1), "=r"(R2), "=r"(R3) : "r"(ADDR))
#define LDSM4T(R0, R1, R2, R3, ADDR)                                                \
    asm volatile("ldmatrix.sync.aligned.m8n8.x4.trans.shared.b16 {%0,%1,%2,%3},[%4];" \
                 : "=r"(R0), "=r"(R1), "=r"(R2), "=r"(R3) : "r"(ADDR))
#define STS64(ADDR, V0, V1)                                                         \
    asm volatile("st.shared.v2.b32 [%0],{%1,%2};" :: "r"(ADDR), "r"(V0), "r"(V1))
#define STS32(ADDR, V0) asm volatile("st.shared.b32 [%0],%1;" :: "r"(ADDR), "r"(V0))
#define CP16(saddr, gptr)                                                           \
    asm volatile("cp.async.cg.shared.global [%0], [%1], 16;" :: "r"(saddr), "l"(gptr))
#define CP_COMMIT() asm volatile("cp.async.commit_group;" ::: "memory")

// ======================================================================
// WIDE fp16x2 GEMM: BM=128, BN=256, BK=32, 512 thr, warps 4(M)x4(N), warp 32x64
// smem/stage: A(fp16) 0..10240 pitch 80 | Bh 10240..27136 pitch 528 | Bl ..44032
#define W_STG 44032
#define W_BH  10240u
#define W_BL  27136u

template <bool ROPE, bool OUTH>
__global__ void __launch_bounds__(512, 1) gemm_h2w(
    const float* __restrict__ A, int lda,
    const float* __restrict__ B, int ldb,
    void* __restrict__ Cout, int ldc,
    int K, const float* __restrict__ cosp, const float* __restrict__ sinp)
{
    extern __shared__ char sh[];
    const int tid = threadIdx.x;
    const int lane = tid & 31, warp = tid >> 5;
    const int g = lane >> 2, t4 = lane & 3;
    const int wm = (warp & 3) * 32, wn = (warp >> 2) * 64;
    const int bm = blockIdx.y * 128, bn = blockIdx.x * 256;

    uint32_t sbase;
    asm("{ .reg .u64 t; cvta.to.shared.u64 t, %1; cvt.u32.u64 %0, t; }"
        : "=r"(sbase) : "l"(sh));

    // A: 128x32 floats -> 2 float4/thread; B: 32x256 floats -> 4 float4/thread
    const float* pA[2];
    uint32_t sA[2];
#pragma unroll
    for (int j = 0; j < 2; j++) {
        int idx = tid + j * 512;
        int r = idx >> 3, c4 = idx & 7;
        pA[j] = A + (size_t)(bm + r) * lda + c4 * 4;
        sA[j] = sbase + (uint32_t)(r * 80 + c4 * 8);
    }
    const float* pB[4];
    uint32_t sB[4];
#pragma unroll
    for (int j = 0; j < 4; j++) {
        int idx = tid + j * 512;
        int kr = idx >> 6, n4 = idx & 63;
        pB[j] = B + (size_t)kr * ldb + bn + n4 * 4;
        sB[j] = sbase + W_BH + (uint32_t)(kr * 528 + n4 * 8);
    }

    const int lr = (lane & 7) + ((lane >> 3) & 1) * 8;
    const int lk = lane >> 4;
    uint32_t aAddr[2], bAddr[4];
#pragma unroll
    for (int mi = 0; mi < 2; mi++)
        aAddr[mi] = sbase + (uint32_t)((wm + mi * 16 + lr) * 80 + lk * 16);
#pragma unroll
    for (int nb = 0; nb < 4; nb++) {
        int kk = (lane & 7) + lk * 8;
        int nc = (wn >> 3) + nb * 2 + ((lane >> 3) & 1);
        bAddr[nb] = sbase + W_BH + (uint32_t)(kk * 528 + nc * 16);
    }

    float acc[2][8][4];
#pragma unroll
    for (int i = 0; i < 2; i++)
#pragma unroll
        for (int j = 0; j < 8; j++)
#pragma unroll
            for (int l = 0; l < 4; l++) acc[i][j][l] = 0.f;

    float4 ra[2], rb[4];
    auto ldg = [&]() {
#pragma unroll
        for (int j = 0; j < 2; j++) { ra[j] = *(const float4*)pA[j]; pA[j] += 32; }
#pragma unroll
        for (int j = 0; j < 4; j++) { rb[j] = *(const float4*)pB[j]; pB[j] += (size_t)32 * ldb; }
    };
    auto sts = [&](int st) {
        uint32_t so = (uint32_t)st * W_STG;
#pragma unroll
        for (int j = 0; j < 2; j++) {
            __half2 a0 = __floats2half2_rn(ra[j].x, ra[j].y);
            __half2 a1 = __floats2half2_rn(ra[j].z, ra[j].w);
            STS64(sA[j] + so, *(uint32_t*)&a0, *(uint32_t*)&a1);
        }
#pragma unroll
        for (int j = 0; j < 4; j++) {
            uint32_t h0, h1, l0, l1;
            splitH4(rb[j], h0, h1, l0, l1);
            STS64(sB[j] + so, h0, h1);
            STS64(sB[j] + so + (W_BL - W_BH), l0, l1);
        }
    };

    const int nK = K >> 5;
    ldg();
    sts(0);
    __syncthreads();

    for (int t = 0; t < nK; t++) {
        const bool more = (t + 1 < nK);
        if (more) ldg();
        const uint32_t so = (uint32_t)(t & 1) * W_STG;
#pragma unroll
        for (int kb = 0; kb < 2; kb++) {
            uint32_t AH[2][4], BH[8][2], BL[8][2];
#pragma unroll
            for (int mi = 0; mi < 2; mi++)
                LDSM4(AH[mi][0], AH[mi][1], AH[mi][2], AH[mi][3],
                      aAddr[mi] + so + kb * 32);
#pragma unroll
            for (int nb = 0; nb < 4; nb++) {
                uint32_t q0, q1, q2, q3;
                uint32_t bd = bAddr[nb] + so + kb * (16 * 528);
                LDSM4T(q0, q1, q2, q3, bd);
                BH[2 * nb][0] = q0; BH[2 * nb][1] = q2;
                BH[2 * nb + 1][0] = q1; BH[2 * nb + 1][1] = q3;
                LDSM4T(q0, q1, q2, q3, bd + (W_BL - W_BH));
                BL[2 * nb][0] = q0; BL[2 * nb][1] = q2;
                BL[2 * nb + 1][0] = q1; BL[2 * nb + 1][1] = q3;
            }
#pragma unroll
            for (int mi = 0; mi < 2; mi++)
#pragma unroll
                for (int ni = 0; ni < 8; ni++) {
                    MMAH16816(acc[mi][ni], AH[mi][0], AH[mi][1], AH[mi][2], AH[mi][3],
                              BL[ni][0], BL[ni][1]);
                    MMAH16816(acc[mi][ni], AH[mi][0], AH[mi][1], AH[mi][2], AH[mi][3],
                              BH[ni][0], BH[ni][1]);
                }
        }
        if (more) sts((t + 1) & 1);
        __syncthreads();
    }

#pragma unroll
    for (int mi = 0; mi < 2; mi++) {
        int rowg = bm + wm + mi * 16 + g;
#pragma unroll
        for (int ni = 0; ni < 8; ni++) {
            int colg = bn + wn + ni * 8 + 2 * t4;
            float c0 = acc[mi][ni][0], c1 = acc[mi][ni][1];
            float c2 = acc[mi][ni][2], c3 = acc[mi][ni][3];
            if (ROPE) {
                int i = (colg & 127) >> 1;
                float cs = cosp[rowg * 64 + i], sn = sinp[rowg * 64 + i];
                float cs2 = cosp[(rowg + 8) * 64 + i], sn2 = sinp[(rowg + 8) * 64 + i];
                float o0 = c0 * cs - c1 * sn, o1 = c0 * sn + c1 * cs;
                float o2 = c2 * cs2 - c3 * sn2, o3 = c2 * sn2 + c3 * cs2;
                c0 = o0; c1 = o1; c2 = o2; c3 = o3;
            }
            if (OUTH) {
                __half* Ch = (__half*)Cout;
                *(__half2*)(Ch + (size_t)rowg * ldc + colg) = __floats2half2_rn(c0, c1);
                *(__half2*)(Ch + (size_t)(rowg + 8) * ldc + colg) = __floats2half2_rn(c2, c3);
            } else {
                float* Cf = (float*)Cout;
                *(float2*)(Cf + (size_t)rowg * ldc + colg) = make_float2(c0, c1);
                *(float2*)(Cf + (size_t)(rowg + 8) * ldc + colg) = make_float2(c2, c3);
            }
        }
    }
}

// ======== narrow fp16x2 GEMM (K/V projections), BM=BN=128 (R11 passing) ========
#define H2_STG 27648
#define H2_BH  10240u
#define H2_BL  18944u

template <bool ROPE, bool OUTH>
__global__ void __launch_bounds__(512, 1) gemm_h2(
    const float* __restrict__ A, int lda,
    const float* __restrict__ B, int ldb,
    void* __restrict__ Cout, int ldc,
    int K, const float* __restrict__ cosp, const float* __restrict__ sinp)
{
    extern __shared__ char sh[];
    const int tid = threadIdx.x;
    const int lane = tid & 31, warp = tid >> 5;
    const int g = lane >> 2, t4 = lane & 3;
    const int wm = (warp & 3) * 32, wn = (warp >> 2) * 32;
    const int bm = blockIdx.y * 128, bn = blockIdx.x * 128;

    uint32_t sbase;
    asm("{ .reg .u64 t; cvta.to.shared.u64 t, %1; cvt.u32.u64 %0, t; }"
        : "=r"(sbase) : "l"(sh));

    const float* pA[2];
    const float* pB[2];
    uint32_t sA[2], sB[2];
#pragma unroll
    for (int j = 0; j < 2; j++) {
        int idx = tid + j * 512;
        int r = idx >> 3, c4 = idx & 7;
        pA[j] = A + (size_t)(bm + r) * lda + c4 * 4;
        sA[j] = sbase + (uint32_t)(r * 80 + c4 * 8);
        int kr = idx >> 5, n4 = idx & 31;
        pB[j] = B + (size_t)kr * ldb + bn + n4 * 4;
        sB[j] = sbase + H2_BH + (uint32_t)(kr * 272 + n4 * 8);
    }

    const int lr = (lane & 7) + ((lane >> 3) & 1) * 8;
    const int lk = lane >> 4;
    uint32_t aAddr[2], bAddr[2];
#pragma unroll
    for (int mi = 0; mi < 2; mi++)
        aAddr[mi] = sbase + (uint32_t)((wm + mi * 16 + lr) * 80 + lk * 16);
#pragma unroll
    for (int nb = 0; nb < 2; nb++) {
        int kk = (lane & 7) + lk * 8;
        int nc = (wn >> 3) + nb * 2 + ((lane >> 3) & 1);
        bAddr[nb] = sbase + H2_BH + (uint32_t)(kk * 272 + nc * 16);
    }

    float acc[2][4][4];
#pragma unroll
    for (int i = 0; i < 2; i++)
#pragma unroll
        for (int j = 0; j < 4; j++)
#pragma unroll
            for (int l = 0; l < 4; l++) acc[i][j][l] = 0.f;

    float4 ra[2], rb[2];
    auto ldg = [&]() {
#pragma unroll
        for (int j = 0; j < 2; j++) {
            ra[j] = *(const float4*)pA[j];
            rb[j] = *(const float4*)pB[j];
            pA[j] += 32;
            pB[j] += (size_t)32 * ldb;
        }
    };
    auto sts = [&](int st) {
        uint32_t so = (uint32_t)st * H2_STG;
#pragma unroll
        for (int j = 0; j < 2; j++) {
            __half2 a0 = __floats2half2_rn(ra[j].x, ra[j].y);
            __half2 a1 = __floats2half2_rn(ra[j].z, ra[j].w);
            STS64(sA[j] + so, *(uint32_t*)&a0, *(uint32_t*)&a1);
            uint32_t h0, h1, l0, l1;
            splitH4(rb[j], h0, h1, l0, l1);
            STS64(sB[j] + so, h0, h1);
            STS64(sB[j] + so + (H2_BL - H2_BH), l0, l1);
        }
    };

    const int nK = K >> 5;
    ldg();
    sts(0);
    __syncthreads();

    for (int t = 0; t < nK; t++) {
        const bool more = (t + 1 < nK);
        if (more) ldg();
        const uint32_t so = (uint32_t)(t & 1) * H2_STG;
#pragma unroll
        for (int kb = 0; kb < 2; kb++) {
            uint32_t AH[2][4], BH[4][2], BL[4][2];
#pragma unroll
            for (int mi = 0; mi < 2; mi++)
                LDSM4(AH[mi][0], AH[mi][1], AH[mi][2], AH[mi][3],
                      aAddr[mi] + so + kb * 32);
#pragma unroll
            for (int nb = 0; nb < 2; nb++) {
                uint32_t q0, q1, q2, q3;
                uint32_t bd = bAddr[nb] + so + kb * (16 * 272);
                LDSM4T(q0, q1, q2, q3, bd);
                BH[2 * nb][0] = q0; BH[2 * nb][1] = q2;
                BH[2 * nb + 1][0] = q1; BH[2 * nb + 1][1] = q3;
                LDSM4T(q0, q1, q2, q3, bd + (H2_BL - H2_BH));
                BL[2 * nb][0] = q0; BL[2 * nb][1] = q2;
                BL[2 * nb + 1][0] = q1; BL[2 * nb + 1][1] = q3;
            }
#pragma unroll
            for (int mi = 0; mi < 2; mi++)
#pragma unroll
                for (int ni = 0; ni < 4; ni++) {
                    MMAH16816(acc[mi][ni], AH[mi][0], AH[mi][1], AH[mi][2], AH[mi][3],
                              BL[ni][0], BL[ni][1]);
                    MMAH16816(acc[mi][ni], AH[mi][0], AH[mi][1], AH[mi][2], AH[mi][3],
                              BH[ni][0], BH[ni][1]);
                }
        }
        if (more) sts((t + 1) & 1);
        __syncthreads();
    }

#pragma unroll
    for (int mi = 0; mi < 2; mi++) {
        int rowg = bm + wm + mi * 16 + g;
#pragma unroll
        for (int ni = 0; ni < 4; ni++) {
            int colg = bn + wn + ni * 8 + 2 * t4;
            float c0 = acc[mi][ni][0], c1 = acc[mi][ni][1];
            float c2 = acc[mi][ni][2], c3 = acc[mi][ni][3];
            if (ROPE) {
                int i = (colg & 127) >> 1;
                float cs = cosp[rowg * 64 + i], sn = sinp[rowg * 64 + i];
                float cs2 = cosp[(rowg + 8) * 64 + i], sn2 = sinp[(rowg + 8) * 64 + i];
                float o0 = c0 * cs - c1 * sn, o1 = c0 * sn + c1 * cs;
                float o2 = c2 * cs2 - c3 * sn2, o3 = c2 * sn2 + c3 * cs2;
                c0 = o0; c1 = o1; c2 = o2; c3 = o3;
            }
            if (OUTH) {
                __half* Ch = (__half*)Cout;
                *(__half2*)(Ch + (size_t)rowg * ldc + colg) = __floats2half2_rn(c0, c1);
                *(__half2*)(Ch + (size_t)(rowg + 8) * ldc + colg) = __floats2half2_rn(c2, c3);
            } else {
                float* Cf = (float*)Cout;
                *(float2*)(Cf + (size_t)rowg * ldc + colg) = make_float2(c0, c1);
                *(float2*)(Cf + (size_t)(rowg + 8) * ldc + colg) = make_float2(c2, c3);
            }
        }
    }
}

// ======== flash attention (unchanged passing version) ========
#define FK_K   34816u
#define FK_V   104448u
#define FK_P   139264u
#define FK_RED 174080u
#define FK_SM  178176

__global__ void __launch_bounds__(512, 1) flash_k(
    const __half* __restrict__ Qm, const __half* __restrict__ Km,
    const __half* __restrict__ Vm, float* __restrict__ Og, float scale)
{
    extern __shared__ char sh[];
    const int h = blockIdx.y;
    const int bm = blockIdx.x * 128;
    const int tid = threadIdx.x;
    const int lane = tid & 31, warp = tid >> 5;
    const int g = lane >> 2, t4 = lane & 3;
    const int wm = (warp & 3) * 32, wn = (warp >> 2) * 32;
    const int wN = warp >> 2;

    uint32_t sbase;
    asm("{ .reg .u64 t; cvta.to.shared.u64 t, %1; cvt.u32.u64 %0, t; }"
        : "=r"(sbase) : "l"(sh));
    float* redM = (float*)(sh + FK_RED);
    float* redS = redM + 512;

    const __half* Qg = Qm + (size_t)bm * 4096 + h * 128;
    const __half* Kg = Km + (size_t)(h >> 2) * 128;
    const __half* Vg = Vm + (size_t)(h >> 2) * 128;

#pragma unroll
    for (int j = 0; j < 4; j++) {
        int idx = tid + j * 512;
        int r = idx >> 4, c = idx & 15;
        CP16(sbase + (uint32_t)(r * 272 + c * 16), Qg + (size_t)r * 4096 + c * 8);
    }
    CP_COMMIT();

    auto cpK = [&](int t) {
        uint32_t dst = sbase + FK_K + (uint32_t)(t & 1) * 34816u;
        const __half* src = Kg + (size_t)t * 128 * 1024;
#pragma unroll
        for (int j = 0; j < 4; j++) {
            int idx = tid + j * 512;
            int r = idx >> 4, c = idx & 15;
            CP16(dst + (uint32_t)(r * 272 + c * 16), src + (size_t)r * 1024 + c * 8);
        }
        CP_COMMIT();
    };
    auto cpV = [&](int t) {
        uint32_t dst = sbase + FK_V;
        const __half* src = Vg + (size_t)t * 128 * 1024;
#pragma unroll
        for (int j = 0; j < 4; j++) {
            int idx = tid + j * 512;
            int r = idx >> 4, c = idx & 15;
            CP16(dst + (uint32_t)(r * 272 + c * 16), src + (size_t)r * 1024 + c * 8);
        }
        CP_COMMIT();
    };
    cpK(0);
    cpV(0);

    const int lr = (lane & 7) + ((lane >> 3) & 1) * 8;
    const int lk = lane >> 4;
    uint32_t qAddr[2], pAddr[2], kAddr[2], vAddr[2];
#pragma unroll
    for (int mi = 0; mi < 2; mi++) {
        qAddr[mi] = sbase + (uint32_t)((wm + mi * 16 + lr) * 272 + lk * 16);
        pAddr[mi] = sbase + FK_P + (uint32_t)((wm + mi * 16 + lr) * 272 + lk * 16);
    }
#pragma unroll
    for (int nb = 0; nb < 2; nb++) {
        kAddr[nb] = sbase + FK_K + (uint32_t)((wn + nb * 16 + lr) * 272 + lk * 16);
        vAddr[nb] = sbase + FK_V +
                    (uint32_t)(((lane & 7) + lk * 8) * 272 +
                               ((wn >> 3) + nb * 2 + ((lane >> 3) & 1)) * 16);
    }

    float accO[2][4][4];
#pragma unroll
    for (int i = 0; i < 2; i++)
#pragma unroll
        for (int j = 0; j < 4; j++)
#pragma unroll
            for (int l = 0; l < 4; l++) accO[i][j][l] = 0.f;
    float mrow[2][2] = {{-1e30f, -1e30f}, {-1e30f, -1e30f}};
    float lsum[2][2] = {{0.f, 0.f}, {0.f, 0.f}};

    for (int t = 0; t < 16; t++) {
        asm volatile("cp.async.wait_group 1;" ::: "memory");
        __syncthreads();

        float accS[2][4][4];
#pragma unroll
        for (int i = 0; i < 2; i++)
#pragma unroll
            for (int j = 0; j < 4; j++)
#pragma unroll
                for (int l = 0; l < 4; l++) accS[i][j][l] = 0.f;
        const uint32_t kst = (uint32_t)(t & 1) * 34816u;
#pragma unroll
        for (int kk = 0; kk < 8; kk++) {
            uint32_t QA[2][4], KB[4][2];
#pragma unroll
            for (int mi = 0; mi < 2; mi++)
                LDSM4(QA[mi][0], QA[mi][1], QA[mi][2], QA[mi][3], qAddr[mi] + kk * 32);
#pragma unroll
            for (int nb = 0; nb < 2; nb++) {
                uint32_t q0, q1, q2, q3;
                LDSM4(q0, q1, q2, q3, kAddr[nb] + kst + kk * 32);
                KB[2 * nb][0] = q0; KB[2 * nb][1] = q2;
                KB[2 * nb + 1][0] = q1; KB[2 * nb + 1][1] = q3;
            }
#pragma unroll
            for (int mi = 0; mi < 2; mi++)
#pragma unroll
                for (int ni = 0; ni < 4; ni++)
                    MMAH16816(accS[mi][ni], QA[mi][0], QA[mi][1], QA[mi][2], QA[mi][3],
                              KB[ni][0], KB[ni][1]);
        }
        if (t < 15) cpK(t + 1);

        float tm[2][2] = {{-1e30f, -1e30f}, {-1e30f, -1e30f}};
#pragma unroll
        for (int mi = 0; mi < 2; mi++)
#pragma unroll
            for (int ni = 0; ni < 4; ni++) {
                accS[mi][ni][0] *= scale; accS[mi][ni][1] *= scale;
                accS[mi][ni][2] *= scale; accS[mi][ni][3] *= scale;
                tm[mi][0] = fmaxf(tm[mi][0], fmaxf(accS[mi][ni][0], accS[mi][ni][1]));
                tm[mi][1] = fmaxf(tm[mi][1], fmaxf(accS[mi][ni][2], accS[mi][ni][3]));
            }
#pragma unroll
        for (int mi = 0; mi < 2; mi++)
#pragma unroll
            for (int hh = 0; hh < 2; hh++) {
                tm[mi][hh] = fmaxf(tm[mi][hh], __shfl_xor_sync(0xffffffffu, tm[mi][hh], 1));
                tm[mi][hh] = fmaxf(tm[mi][hh], __shfl_xor_sync(0xffffffffu, tm[mi][hh], 2));
            }
        if (t4 == 0)
#pragma unroll
            for (int mi = 0; mi < 2; mi++)
#pragma unroll
                for (int hh = 0; hh < 2; hh++)
                    redM[wN * 128 + wm + mi * 16 + g + hh * 8] = tm[mi][hh];
        __syncthreads();

        float Mn[2][2], al[2][2];
#pragma unroll
        for (int mi = 0; mi < 2; mi++)
#pragma unroll
            for (int hh = 0; hh < 2; hh++) {
                int row = wm + mi * 16 + g + hh * 8;
                float m = fmaxf(fmaxf(redM[row], redM[128 + row]),
                                fmaxf(redM[256 + row], redM[384 + row]));
                Mn[mi][hh] = fmaxf(mrow[mi][hh], m);
                al[mi][hh] = __expf(mrow[mi][hh] - Mn[mi][hh]);
                mrow[mi][hh] = Mn[mi][hh];
            }

        float rs[2][2] = {{0.f, 0.f}, {0.f, 0.f}};
#pragma unroll
        for (int mi = 0; mi < 2; mi++)
#pragma unroll
            for (int ni = 0; ni < 4; ni++) {
                float p0 = __expf(accS[mi][ni][0] - Mn[mi][0]);
                float p1 = __expf(accS[mi][ni][1] - Mn[mi][0]);
                float p2 = __expf(accS[mi][ni][2] - Mn[mi][1]);
                float p3 = __expf(accS[mi][ni][3] - Mn[mi][1]);
                rs[mi][0] += p0 + p1;
                rs[mi][1] += p2 + p3;
                __half2 hA = __floats2half2_rn(p0, p1);
                __half2 hB = __floats2half2_rn(p2, p3);
                uint32_t a0 = sbase + FK_P +
                              (uint32_t)((wm + mi * 16 + g) * 272 + (wn + ni * 8 + 2 * t4) * 2);
                STS32(a0, *(uint32_t*)&hA);
                STS32(a0 + 8 * 272, *(uint32_t*)&hB);
            }
#pragma unroll
        for (int mi = 0; mi < 2; mi++)
#pragma unroll
            for (int hh = 0; hh < 2; hh++) {
                rs[mi][hh] += __shfl_xor_sync(0xffffffffu, rs[mi][hh], 1);
                rs[mi][hh] += __shfl_xor_sync(0xffffffffu, rs[mi][hh], 2);
            }
        if (t4 == 0)
#pragma unroll
            for (int mi = 0; mi < 2; mi++)
#pragma unroll
                for (int hh = 0; hh < 2; hh++)
                    redS[wN * 128 + wm + mi * 16 + g + hh * 8] = rs[mi][hh];
        if (t < 15) asm volatile("cp.async.wait_group 1;" ::: "memory");
        else        asm volatile("cp.async.wait_group 0;" ::: "memory");
        __syncthreads();

#pragma unroll
        for (int mi = 0; mi < 2; mi++)
#pragma unroll
            for (int hh = 0; hh < 2; hh++) {
                int row = wm + mi * 16 + g + hh * 8;
                float rsum = redS[row] + redS[128 + row] + redS[256 + row] + redS[384 + row];
                lsum[mi][hh] = lsum[mi][hh] * al[mi][hh] + rsum;
            }
#pragma unroll
        for (int mi = 0; mi < 2; mi++)
#pragma unroll
            for (int ni = 0; ni < 4; ni++) {
                accO[mi][ni][0] *= al[mi][0]; accO[mi][ni][1] *= al[mi][0];
                accO[mi][ni][2] *= al[mi][1]; accO[mi][ni][3] *= al[mi][1];
            }

#pragma unroll
        for (int kk = 0; kk < 8; kk++) {
            uint32_t PA[2][4], VB[4][2];
#pragma unroll
            for (int mi = 0; mi < 2; mi++)
                LDSM4(PA[mi][0], PA[mi][1], PA[mi][2], PA[mi][3], pAddr[mi] + kk * 32);
#pragma unroll
            for (int nb = 0; nb < 2; nb++) {
                uint32_t q0, q1, q2, q3;
                LDSM4T(q0, q1, q2, q3, vAddr[nb] + kk * (16 * 272));
                VB[2 * nb][0] = q0; VB[2 * nb][1] = q2;
                VB[2 * nb + 1][0] = q1; VB[2 * nb + 1][1] = q3;
            }
#pragma unroll
            for (int mi = 0; mi < 2; mi++)
#pragma unroll
                for (int ni = 0; ni < 4; ni++)
                    MMAH16816(accO[mi][ni], PA[mi][0], PA[mi][1], PA[mi][2], PA[mi][3],
                              VB[ni][0], VB[ni][1]);
        }
        __syncthreads();
        if (t < 15) cpV(t + 1);
    }

    float inv[2][2];
#pragma unroll
    for (int mi = 0; mi < 2; mi++)
#pragma unroll
        for (int hh = 0; hh < 2; hh++) inv[mi][hh] = 1.0f / lsum[mi][hh];
#pragma unroll
    for (int mi = 0; mi < 2; mi++) {
        int rowg = bm + wm + mi * 16 + g;
#pragma unroll
        for (int ni = 0; ni < 4; ni++) {
            int colg = h * 128 + wn + ni * 8 + 2 * t4;
            *(float2*)(Og + (size_t)rowg * 4096 + colg) =
                make_float2(accO[mi][ni][0] * inv[mi][0], accO[mi][ni][1] * inv[mi][0]);
            *(float2*)(Og + (size_t)(rowg + 8) * 4096 + colg) =
                make_float2(accO[mi][ni][2] * inv[mi][1], accO[mi][ni][3] * inv[mi][1]);
        }
    }
}

extern "C" void kernel_launch(void* const* d_in, const int* in_sizes, int n_in,
                              void* d_out, int out_size) {
    const float* x  = (const float*)d_in[0];
    const float* fc = (const float*)d_in[1];
    const float* fs = (const float*)d_in[2];
    const float* wq = (const float*)d_in[3];
    const float* wk = (const float*)d_in[4];
    const float* wv = (const float*)d_in[5];
    const float* wo = (const float*)d_in[6];
    float* out = (float*)d_out;

    __half *qh, *kh, *vh;
    float* o;
    cudaGetSymbolAddress((void**)&qh, g_qh);
    cudaGetSymbolAddress((void**)&kh, g_kh);
    cudaGetSymbolAddress((void**)&vh, g_vh);
    cudaGetSymbolAddress((void**)&o,  g_o);

    const int SMW = 2 * W_STG;   // 88064
    const int SM  = 2 * H2_STG;  // 55296
    cudaFuncSetAttribute(gemm_h2w<true,  true >, cudaFuncAttributeMaxDynamicSharedMemorySize, SMW);
    cudaFuncSetAttribute(gemm_h2w<false, false>, cudaFuncAttributeMaxDynamicSharedMemorySize, SMW);
    cudaFuncSetAttribute(gemm_h2<true,  true >, cudaFuncAttributeMaxDynamicSharedMemorySize, SM);
    cudaFuncSetAttribute(gemm_h2<false, true >, cudaFuncAttributeMaxDynamicSharedMemorySize, SM);
    cudaFuncSetAttribute(flash_k, cudaFuncAttributeMaxDynamicSharedMemorySize, FK_SM);

    const dim3 blk(512);
    const float scale = 0.08838834764831845f;  // 1/sqrt(128)

    gemm_h2w<true,  true ><<<dim3(16, 16), blk, SMW>>>(x, 4096, wq, 4096, qh, 4096, 4096, fc, fs);
    gemm_h2 <true,  true ><<<dim3( 8, 16), blk, SM >>>(x, 4096, wk, 1024, kh, 1024, 4096, fc, fs);
    gemm_h2 <false, true ><<<dim3( 8, 16), blk, SM >>>(x, 4096, wv, 1024, vh, 1024, 4096, nullptr, nullptr);
    flash_k<<<dim3(16, NHEADS), blk, FK_SM>>>(qh, kh, vh, o, scale);
    gemm_h2w<false, false><<<dim3(16, 16), blk, SMW>>>(o, 4096, wo, 4096, out, 4096, 4096, nullptr, nullptr);
}

// round 14
// speedup vs baseline: 3.2738x; 1.1302x over previous
#include <cuda_runtime.h>
#include <cuda_fp16.h>
#include <cstdint>
#include <cstddef>

#define SEQ 2048
#define NHEADS 32

// ---------------- device scratch (fp16 planes) ----------------
__device__ __half g_xh[SEQ * 4096];
__device__ __half g_wqh[4096 * 4096], g_wql[4096 * 4096];
__device__ __half g_wkvh[4096 * 2048], g_wkvl[4096 * 2048];
__device__ __half g_woh[4096 * 4096], g_wol[4096 * 4096];
__device__ __half g_qh[SEQ * 4096];
__device__ __half g_kvh[SEQ * 2048];
__device__ __half g_ohh[SEQ * 4096];

#define MMAH16816(C, A0, A1, A2, A3, B0, B1)                                        \
    asm volatile(                                                                   \
        "mma.sync.aligned.m16n8k16.row.col.f32.f16.f16.f32 "                        \
        "{%0,%1,%2,%3},{%4,%5,%6,%7},{%8,%9},{%0,%1,%2,%3};"                        \
        : "+f"((C)[0]), "+f"((C)[1]), "+f"((C)[2]), "+f"((C)[3])                    \
        : "r"(A0), "r"(A1), "r"(A2), "r"(A3), "r"(B0), "r"(B1))
#define LDSM4(R0, R1, R2, R3, ADDR)                                                 \
    asm volatile("ldmatrix.sync.aligned.m8n8.x4.shared.b16 {%0,%1,%2,%3},[%4];"     \
                 : "=r"(R0), "=r"(R1), "=r"(R2), "=r"(R3) : "r"(ADDR))
#define LDSM4T(R0, R1, R2, R3, ADDR)                                                \
    asm volatile("ldmatrix.sync.aligned.m8n8.x4.trans.shared.b16 {%0,%1,%2,%3},[%4];" \
                 : "=r"(R0), "=r"(R1), "=r"(R2), "=r"(R3) : "r"(ADDR))
#define STS32(ADDR, V0) asm volatile("st.shared.b32 [%0],%1;" :: "r"(ADDR), "r"(V0))
#define CP16(saddr, gptr)                                                           \
    asm volatile("cp.async.cg.shared.global [%0], [%1], 16;" :: "r"(saddr), "l"(gptr))
#define CP_COMMIT() asm volatile("cp.async.commit_group;" ::: "memory")

// ---------------- prep kernels (one-time conversion) ----------------
__global__ void cvt_x(const float* __restrict__ in, __half* __restrict__ out, int n4) {
    int i = blockIdx.x * blockDim.x + threadIdx.x;
    if (i >= n4) return;
    float4 f = ((const float4*)in)[i];
    __half2 a = __floats2half2_rn(f.x, f.y);
    __half2 b = __floats2half2_rn(f.z, f.w);
    __half2* o = (__half2*)(out + (size_t)i * 4);
    o[0] = a; o[1] = b;
}

// w fp32 [4096][N] -> fp16 hi/lo planes [4096][ldo] at column offset co
__global__ void splitw(const float* __restrict__ w, int N4,
                       __half* __restrict__ wh, __half* __restrict__ wl,
                       int ldo, int co) {
    int i = blockIdx.x * blockDim.x + threadIdx.x;
    if (i >= 4096 * N4) return;
    int row = i / N4, c4 = i - row * N4;
    float4 f = ((const float4*)w)[i];
    __half2 h0 = __floats2half2_rn(f.x, f.y);
    __half2 h1 = __floats2half2_rn(f.z, f.w);
    float2 h0f = __half22float2(h0), h1f = __half22float2(h1);
    __half2 l0 = __floats2half2_rn(f.x - h0f.x, f.y - h0f.y);
    __half2 l1 = __floats2half2_rn(f.z - h1f.x, f.w - h1f.y);
    size_t off = (size_t)row * ldo + co + c4 * 4;
    ((__half2*)(wh + off))[0] = h0; ((__half2*)(wh + off))[1] = h1;
    ((__half2*)(wl + off))[0] = l0; ((__half2*)(wl + off))[1] = l1;
}

// ======================================================================
// preconverted fp16x2 GEMM: C[2048 x N] = A16 * (Bh + Bl), BM=128 BN=256 BK=32
// 512 thr, warps 4(M)x4(N), warp tile 32x64. Pure cp.async mainloop.
// smem/stage: A 0..10240 (pitch 80) | Bh 10240..27136 (pitch 528) | Bl ..44032
#define W_STG 44032
#define W_BH  10240u
#define W_BL  27136u

template <bool OUTH>
__global__ void __launch_bounds__(512, 1) gemm_pc(
    const __half* __restrict__ A, int lda,
    const __half* __restrict__ Bh, const __half* __restrict__ Bl, int ldb,
    void* __restrict__ Cout, int ldc, int ropeLim,
    const float* __restrict__ cosp, const float* __restrict__ sinp)
{
    extern __shared__ char sh[];
    const int tid = threadIdx.x;
    const int lane = tid & 31, warp = tid >> 5;
    const int g = lane >> 2, t4 = lane & 3;
    const int wm = (warp & 3) * 32, wn = (warp >> 2) * 64;
    const int bm = blockIdx.y * 128, bn = blockIdx.x * 256;

    uint32_t sbase;
    asm("{ .reg .u64 t; cvta.to.shared.u64 t, %1; cvt.u32.u64 %0, t; }"
        : "=r"(sbase) : "l"(sh));

    // cp.async coords: A 1 chunk/thread, B 2+2 chunks/thread
    const int ar = tid >> 2, ac = tid & 3;
    const uint32_t aDst = (uint32_t)(ar * 80 + ac * 16);
    const __half* aSrc = A + (size_t)(bm + ar) * lda + ac * 8;
    uint32_t bDst[2];
    const __half* bSrcH[2];
    const __half* bSrcL[2];
#pragma unroll
    for (int j = 0; j < 2; j++) {
        int idx = tid + j * 512;
        int kr = idx >> 5, c = idx & 31;
        bDst[j] = W_BH + (uint32_t)(kr * 528 + c * 16);
        bSrcH[j] = Bh + (size_t)kr * ldb + bn + c * 8;
        bSrcL[j] = Bl + (size_t)kr * ldb + bn + c * 8;
    }

    auto loadStage = [&](int t) {
        const uint32_t so = sbase + (uint32_t)(t & 1) * W_STG;
        const size_t ko = (size_t)t * 32;
        CP16(so + aDst, aSrc + ko);
#pragma unroll
        for (int j = 0; j < 2; j++) {
            CP16(so + bDst[j], bSrcH[j] + ko * ldb);
            CP16(so + bDst[j] + (W_BL - W_BH), bSrcL[j] + ko * ldb);
        }
        CP_COMMIT();
    };

    const int lr = (lane & 7) + ((lane >> 3) & 1) * 8;
    const int lk = lane >> 4;
    uint32_t aAddr[2], bAddr[4];
#pragma unroll
    for (int mi = 0; mi < 2; mi++)
        aAddr[mi] = sbase + (uint32_t)((wm + mi * 16 + lr) * 80 + lk * 16);
#pragma unroll
    for (int nb = 0; nb < 4; nb++) {
        int kk = (lane & 7) + lk * 8;
        int nc = (wn >> 3) + nb * 2 + ((lane >> 3) & 1);
        bAddr[nb] = sbase + W_BH + (uint32_t)(kk * 528 + nc * 16);
    }

    float acc[2][8][4];
#pragma unroll
    for (int i = 0; i < 2; i++)
#pragma unroll
        for (int j = 0; j < 8; j++)
#pragma unroll
            for (int l = 0; l < 4; l++) acc[i][j][l] = 0.f;

    const int nK = 128;  // K = 4096
    loadStage(0);

    for (int t = 0; t < nK; t++) {
        asm volatile("cp.async.wait_group 0;" ::: "memory");
        __syncthreads();
        if (t + 1 < nK) loadStage(t + 1);
        const uint32_t so = (uint32_t)(t & 1) * W_STG;
#pragma unroll
        for (int kb = 0; kb < 2; kb++) {
            uint32_t AH[2][4], BH[8][2], BL[8][2];
#pragma unroll
            for (int mi = 0; mi < 2; mi++)
                LDSM4(AH[mi][0], AH[mi][1], AH[mi][2], AH[mi][3],
                      aAddr[mi] + so + kb * 32);
#pragma unroll
            for (int nb = 0; nb < 4; nb++) {
                uint32_t q0, q1, q2, q3;
                uint32_t bd = bAddr[nb] + so + kb * (16 * 528);
                LDSM4T(q0, q1, q2, q3, bd);
                BH[2 * nb][0] = q0; BH[2 * nb][1] = q2;
                BH[2 * nb + 1][0] = q1; BH[2 * nb + 1][1] = q3;
                LDSM4T(q0, q1, q2, q3, bd + (W_BL - W_BH));
                BL[2 * nb][0] = q0; BL[2 * nb][1] = q2;
                BL[2 * nb + 1][0] = q1; BL[2 * nb + 1][1] = q3;
            }
#pragma unroll
            for (int mi = 0; mi < 2; mi++)
#pragma unroll
                for (int ni = 0; ni < 8; ni++) {
                    MMAH16816(acc[mi][ni], AH[mi][0], AH[mi][1], AH[mi][2], AH[mi][3],
                              BL[ni][0], BL[ni][1]);
                    MMAH16816(acc[mi][ni], AH[mi][0], AH[mi][1], AH[mi][2], AH[mi][3],
                              BH[ni][0], BH[ni][1]);
                }
        }
    }

#pragma unroll
    for (int mi = 0; mi < 2; mi++) {
        int rowg = bm + wm + mi * 16 + g;
#pragma unroll
        for (int ni = 0; ni < 8; ni++) {
            int colg = bn + wn + ni * 8 + 2 * t4;
            float c0 = acc[mi][ni][0], c1 = acc[mi][ni][1];
            float c2 = acc[mi][ni][2], c3 = acc[mi][ni][3];
            if (colg < ropeLim) {
                int i = (colg & 127) >> 1;
                float cs = cosp[rowg * 64 + i], sn = sinp[rowg * 64 + i];
                float cs2 = cosp[(rowg + 8) * 64 + i], sn2 = sinp[(rowg + 8) * 64 + i];
                float o0 = c0 * cs - c1 * sn, o1 = c0 * sn + c1 * cs;
                float o2 = c2 * cs2 - c3 * sn2, o3 = c2 * sn2 + c3 * cs2;
                c0 = o0; c1 = o1; c2 = o2; c3 = o3;
            }
            if (OUTH) {
                __half* Ch = (__half*)Cout;
                *(__half2*)(Ch + (size_t)rowg * ldc + colg) = __floats2half2_rn(c0, c1);
                *(__half2*)(Ch + (size_t)(rowg + 8) * ldc + colg) = __floats2half2_rn(c2, c3);
            } else {
                float* Cf = (float*)Cout;
                *(float2*)(Cf + (size_t)rowg * ldc + colg) = make_float2(c0, c1);
                *(float2*)(Cf + (size_t)(rowg + 8) * ldc + colg) = make_float2(c2, c3);
            }
        }
    }
}

// ======== flash attention (K/V from merged [2048][2048] buffer; O -> fp16) ====
#define FK_K   34816u
#define FK_V   104448u
#define FK_P   139264u
#define FK_RED 174080u
#define FK_SM  178176

__global__ void __launch_bounds__(512, 1) flash_k(
    const __half* __restrict__ Qm, const __half* __restrict__ KVm,
    __half* __restrict__ Oh, float scale)
{
    extern __shared__ char sh[];
    const int h = blockIdx.y;
    const int bm = blockIdx.x * 128;
    const int tid = threadIdx.x;
    const int lane = tid & 31, warp = tid >> 5;
    const int g = lane >> 2, t4 = lane & 3;
    const int wm = (warp & 3) * 32, wn = (warp >> 2) * 32;
    const int wN = warp >> 2;

    uint32_t sbase;
    asm("{ .reg .u64 t; cvta.to.shared.u64 t, %1; cvt.u32.u64 %0, t; }"
        : "=r"(sbase) : "l"(sh));
    float* redM = (float*)(sh + FK_RED);
    float* redS = redM + 512;

    const __half* Qg = Qm + (size_t)bm * 4096 + h * 128;
    const __half* Kg = KVm + (size_t)(h >> 2) * 128;
    const __half* Vg = KVm + 1024 + (size_t)(h >> 2) * 128;

#pragma unroll
    for (int j = 0; j < 4; j++) {
        int idx = tid + j * 512;
        int r = idx >> 4, c = idx & 15;
        CP16(sbase + (uint32_t)(r * 272 + c * 16), Qg + (size_t)r * 4096 + c * 8);
    }
    CP_COMMIT();

    auto cpK = [&](int t) {
        uint32_t dst = sbase + FK_K + (uint32_t)(t & 1) * 34816u;
        const __half* src = Kg + (size_t)t * 128 * 2048;
#pragma unroll
        for (int j = 0; j < 4; j++) {
            int idx = tid + j * 512;
            int r = idx >> 4, c = idx & 15;
            CP16(dst + (uint32_t)(r * 272 + c * 16), src + (size_t)r * 2048 + c * 8);
        }
        CP_COMMIT();
    };
    auto cpV = [&](int t) {
        uint32_t dst = sbase + FK_V;
        const __half* src = Vg + (size_t)t * 128 * 2048;
#pragma unroll
        for (int j = 0; j < 4; j++) {
            int idx = tid + j * 512;
            int r = idx >> 4, c = idx & 15;
            CP16(dst + (uint32_t)(r * 272 + c * 16), src + (size_t)r * 2048 + c * 8);
        }
        CP_COMMIT();
    };
    cpK(0);
    cpV(0);

    const int lr = (lane & 7) + ((lane >> 3) & 1) * 8;
    const int lk = lane >> 4;
    uint32_t qAddr[2], pAddr[2], kAddr[2], vAddr[2];
#pragma unroll
    for (int mi = 0; mi < 2; mi++) {
        qAddr[mi] = sbase + (uint32_t)((wm + mi * 16 + lr) * 272 + lk * 16);
        pAddr[mi] = sbase + FK_P + (uint32_t)((wm + mi * 16 + lr) * 272 + lk * 16);
    }
#pragma unroll
    for (int nb = 0; nb < 2; nb++) {
        kAddr[nb] = sbase + FK_K + (uint32_t)((wn + nb * 16 + lr) * 272 + lk * 16);
        vAddr[nb] = sbase + FK_V +
                    (uint32_t)(((lane & 7) + lk * 8) * 272 +
                               ((wn >> 3) + nb * 2 + ((lane >> 3) & 1)) * 16);
    }

    float accO[2][4][4];
#pragma unroll
    for (int i = 0; i < 2; i++)
#pragma unroll
        for (int j = 0; j < 4; j++)
#pragma unroll
            for (int l = 0; l < 4; l++) accO[i][j][l] = 0.f;
    float mrow[2][2] = {{-1e30f, -1e30f}, {-1e30f, -1e30f}};
    float lsum[2][2] = {{0.f, 0.f}, {0.f, 0.f}};

    for (int t = 0; t < 16; t++) {
        asm volatile("cp.async.wait_group 1;" ::: "memory");
        __syncthreads();

        float accS[2][4][4];
#pragma unroll
        for (int i = 0; i < 2; i++)
#pragma unroll
            for (int j = 0; j < 4; j++)
#pragma unroll
                for (int l = 0; l < 4; l++) accS[i][j][l] = 0.f;
        const uint32_t kst = (uint32_t)(t & 1) * 34816u;
#pragma unroll
        for (int kk = 0; kk < 8; kk++) {
            uint32_t QA[2][4], KB[4][2];
#pragma unroll
            for (int mi = 0; mi < 2; mi++)
                LDSM4(QA[mi][0], QA[mi][1], QA[mi][2], QA[mi][3], qAddr[mi] + kk * 32);
#pragma unroll
            for (int nb = 0; nb < 2; nb++) {
                uint32_t q0, q1, q2, q3;
                LDSM4(q0, q1, q2, q3, kAddr[nb] + kst + kk * 32);
                KB[2 * nb][0] = q0; KB[2 * nb][1] = q2;
                KB[2 * nb + 1][0] = q1; KB[2 * nb + 1][1] = q3;
            }
#pragma unroll
            for (int mi = 0; mi < 2; mi++)
#pragma unroll
                for (int ni = 0; ni < 4; ni++)
                    MMAH16816(accS[mi][ni], QA[mi][0], QA[mi][1], QA[mi][2], QA[mi][3],
                              KB[ni][0], KB[ni][1]);
        }
        if (t < 15) cpK(t + 1);

        float tm[2][2] = {{-1e30f, -1e30f}, {-1e30f, -1e30f}};
#pragma unroll
        for (int mi = 0; mi < 2; mi++)
#pragma unroll
            for (int ni = 0; ni < 4; ni++) {
                accS[mi][ni][0] *= scale; accS[mi][ni][1] *= scale;
                accS[mi][ni][2] *= scale; accS[mi][ni][3] *= scale;
                tm[mi][0] = fmaxf(tm[mi][0], fmaxf(accS[mi][ni][0], accS[mi][ni][1]));
                tm[mi][1] = fmaxf(tm[mi][1], fmaxf(accS[mi][ni][2], accS[mi][ni][3]));
            }
#pragma unroll
        for (int mi = 0; mi < 2; mi++)
#pragma unroll
            for (int hh = 0; hh < 2; hh++) {
                tm[mi][hh] = fmaxf(tm[mi][hh], __shfl_xor_sync(0xffffffffu, tm[mi][hh], 1));
                tm[mi][hh] = fmaxf(tm[mi][hh], __shfl_xor_sync(0xffffffffu, tm[mi][hh], 2));
            }
        if (t4 == 0)
#pragma unroll
            for (int mi = 0; mi < 2; mi++)
#pragma unroll
                for (int hh = 0; hh < 2; hh++)
                    redM[wN * 128 + wm + mi * 16 + g + hh * 8] = tm[mi][hh];
        __syncthreads();

        float Mn[2][2], al[2][2];
#pragma unroll
        for (int mi = 0; mi < 2; mi++)
#pragma unroll
            for (int hh = 0; hh < 2; hh++) {
                int row = wm + mi * 16 + g + hh * 8;
                float m = fmaxf(fmaxf(redM[row], redM[128 + row]),
                                fmaxf(redM[256 + row], redM[384 + row]));
                Mn[mi][hh] = fmaxf(mrow[mi][hh], m);
                al[mi][hh] = __expf(mrow[mi][hh] - Mn[mi][hh]);
                mrow[mi][hh] = Mn[mi][hh];
            }

        float rs[2][2] = {{0.f, 0.f}, {0.f, 0.f}};
#pragma unroll
        for (int mi = 0; mi < 2; mi++)
#pragma unroll
            for (int ni = 0; ni < 4; ni++) {
                float p0 = __expf(accS[mi][ni][0] - Mn[mi][0]);
                float p1 = __expf(accS[mi][ni][1] - Mn[mi][0]);
                float p2 = __expf(accS[mi][ni][2] - Mn[mi][1]);
                float p3 = __expf(accS[mi][ni][3] - Mn[mi][1]);
                rs[mi][0] += p0 + p1;
                rs[mi][1] += p2 + p3;
                __half2 hA = __floats2half2_rn(p0, p1);
                __half2 hB = __floats2half2_rn(p2, p3);
                uint32_t a0 = sbase + FK_P +
                              (uint32_t)((wm + mi * 16 + g) * 272 + (wn + ni * 8 + 2 * t4) * 2);
                STS32(a0, *(uint32_t*)&hA);
                STS32(a0 + 8 * 272, *(uint32_t*)&hB);
            }
#pragma unroll
        for (int mi = 0; mi < 2; mi++)
#pragma unroll
            for (int hh = 0; hh < 2; hh++) {
                rs[mi][hh] += __shfl_xor_sync(0xffffffffu, rs[mi][hh], 1);
                rs[mi][hh] += __shfl_xor_sync(0xffffffffu, rs[mi][hh], 2);
            }
        if (t4 == 0)
#pragma unroll
            for (int mi = 0; mi < 2; mi++)
#pragma unroll
                for (int hh = 0; hh < 2; hh++)
                    redS[wN * 128 + wm + mi * 16 + g + hh * 8] = rs[mi][hh];
        if (t < 15) asm volatile("cp.async.wait_group 1;" ::: "memory");
        else        asm volatile("cp.async.wait_group 0;" ::: "memory");
        __syncthreads();

#pragma unroll
        for (int mi = 0; mi < 2; mi++)
#pragma unroll
            for (int hh = 0; hh < 2; hh++) {
                int row = wm + mi * 16 + g + hh * 8;
                float rsum = redS[row] + redS[128 + row] + redS[256 + row] + redS[384 + row];
                lsum[mi][hh] = lsum[mi][hh] * al[mi][hh] + rsum;
            }
#pragma unroll
        for (int mi = 0; mi < 2; mi++)
#pragma unroll
            for (int ni = 0; ni < 4; ni++) {
                accO[mi][ni][0] *= al[mi][0]; accO[mi][ni][1] *= al[mi][0];
                accO[mi][ni][2] *= al[mi][1]; accO[mi][ni][3] *= al[mi][1];
            }

#pragma unroll
        for (int kk = 0; kk < 8; kk++) {
            uint32_t PA[2][4], VB[4][2];
#pragma unroll
            for (int mi = 0; mi < 2; mi++)
                LDSM4(PA[mi][0], PA[mi][1], PA[mi][2], PA[mi][3], pAddr[mi] + kk * 32);
#pragma unroll
            for (int nb = 0; nb < 2; nb++) {
                uint32_t q0, q1, q2, q3;
                LDSM4T(q0, q1, q2, q3, vAddr[nb] + kk * (16 * 272));
                VB[2 * nb][0] = q0; VB[2 * nb][1] = q2;
                VB[2 * nb + 1][0] = q1; VB[2 * nb + 1][1] = q3;
            }
#pragma unroll
            for (int mi = 0; mi < 2; mi++)
#pragma unroll
                for (int ni = 0; ni < 4; ni++)
                    MMAH16816(accO[mi][ni], PA[mi][0], PA[mi][1], PA[mi][2], PA[mi][3],
                              VB[ni][0], VB[ni][1]);
        }
        __syncthreads();
        if (t < 15) cpV(t + 1);
    }

    float inv[2][2];
#pragma unroll
    for (int mi = 0; mi < 2; mi++)
#pragma unroll
        for (int hh = 0; hh < 2; hh++) inv[mi][hh] = 1.0f / lsum[mi][hh];
#pragma unroll
    for (int mi = 0; mi < 2; mi++) {
        int rowg = bm + wm + mi * 16 + g;
#pragma unroll
        for (int ni = 0; ni < 4; ni++) {
            int colg = h * 128 + wn + ni * 8 + 2 * t4;
            *(__half2*)(Oh + (size_t)rowg * 4096 + colg) =
                __floats2half2_rn(accO[mi][ni][0] * inv[mi][0], accO[mi][ni][1] * inv[mi][0]);
            *(__half2*)(Oh + (size_t)(rowg + 8) * 4096 + colg) =
                __floats2half2_rn(accO[mi][ni][2] * inv[mi][1], accO[mi][ni][3] * inv[mi][1]);
        }
    }
}

extern "C" void kernel_launch(void* const* d_in, const int* in_sizes, int n_in,
                              void* d_out, int out_size) {
    const float* x  = (const float*)d_in[0];
    const float* fc = (const float*)d_in[1];
    const float* fs = (const float*)d_in[2];
    const float* wq = (const float*)d_in[3];
    const float* wk = (const float*)d_in[4];
    const float* wv = (const float*)d_in[5];
    const float* wo = (const float*)d_in[6];
    float* out = (float*)d_out;

    __half *xh, *wqh, *wql, *wkvh, *wkvl, *woh, *wol, *qh, *kvh, *ohh;
    cudaGetSymbolAddress((void**)&xh,   g_xh);
    cudaGetSymbolAddress((void**)&wqh,  g_wqh);  cudaGetSymbolAddress((void**)&wql,  g_wql);
    cudaGetSymbolAddress((void**)&wkvh, g_wkvh); cudaGetSymbolAddress((void**)&wkvl, g_wkvl);
    cudaGetSymbolAddress((void**)&woh,  g_woh);  cudaGetSymbolAddress((void**)&wol,  g_wol);
    cudaGetSymbolAddress((void**)&qh,   g_qh);
    cudaGetSymbolAddress((void**)&kvh,  g_kvh);
    cudaGetSymbolAddress((void**)&ohh,  g_ohh);

    const int SMW = 2 * W_STG;  // 88064
    cudaFuncSetAttribute(gemm_pc<true >, cudaFuncAttributeMaxDynamicSharedMemorySize, SMW);
    cudaFuncSetAttribute(gemm_pc<false>, cudaFuncAttributeMaxDynamicSharedMemorySize, SMW);
    cudaFuncSetAttribute(flash_k, cudaFuncAttributeMaxDynamicSharedMemorySize, FK_SM);

    const dim3 blk(512);
    const float scale = 0.08838834764831845f;  // 1/sqrt(128)

    // prep: fp16 planes
    cvt_x<<<8192, 256>>>(x, xh, SEQ * 4096 / 4);
    splitw<<<16384, 256>>>(wq, 1024, wqh, wql, 4096, 0);
    splitw<<< 4096, 256>>>(wk,  256, wkvh, wkvl, 2048, 0);
    splitw<<< 4096, 256>>>(wv,  256, wkvh, wkvl, 2048, 1024);
    splitw<<<16384, 256>>>(wo, 1024, woh, wol, 4096, 0);

    // projections
    gemm_pc<true ><<<dim3(16, 16), blk, SMW>>>(xh, 4096, wqh, wql, 4096, qh, 4096, 4096, fc, fs);
    gemm_pc<true ><<<dim3( 8, 16), blk, SMW>>>(xh, 4096, wkvh, wkvl, 2048, kvh, 2048, 1024, fc, fs);
    // attention
    flash_k<<<dim3(16, NHEADS), blk, FK_SM>>>(qh, kvh, ohh, scale);
    // output projection
    gemm_pc<false><<<dim3(16, 16), blk, SMW>>>(ohh, 4096, woh, wol, 4096, out, 4096, 0, nullptr, nullptr);
}

// round 15
// speedup vs baseline: 3.3643x; 1.0276x over previous
#include <cuda_runtime.h>
#include <cuda_fp16.h>
#include <cstdint>
#include <cstddef>

#define SEQ 2048
#define NHEADS 32

// ---------------- device scratch (fp16 planes) ----------------
__device__ __half g_xh[SEQ * 4096];
__device__ __half g_wqh[4096 * 4096], g_wql[4096 * 4096];
__device__ __half g_wkvh[4096 * 2048], g_wkvl[4096 * 2048];
__device__ __half g_woh[4096 * 4096], g_wol[4096 * 4096];
__device__ __half g_qh[SEQ * 4096];
__device__ __half g_kvh[SEQ * 2048];
__device__ __half g_ohh[SEQ * 4096];

#define MMAH16816(C, A0, A1, A2, A3, B0, B1)                                        \
    asm volatile(                                                                   \
        "mma.sync.aligned.m16n8k16.row.col.f32.f16.f16.f32 "                        \
        "{%0,%1,%2,%3},{%4,%5,%6,%7},{%8,%9},{%0,%1,%2,%3};"                        \
        : "+f"((C)[0]), "+f"((C)[1]), "+f"((C)[2]), "+f"((C)[3])                    \
        : "r"(A0), "r"(A1), "r"(A2), "r"(A3), "r"(B0), "r"(B1))
#define LDSM4(R0, R1, R2, R3, ADDR)                                                 \
    asm volatile("ldmatrix.sync.aligned.m8n8.x4.shared.b16 {%0,%1,%2,%3},[%4];"     \
                 : "=r"(R0), "=r"(R1), "=r"(R2), "=r"(R3) : "r"(ADDR))
#define LDSM4T(R0, R1, R2, R3, ADDR)                                                \
    asm volatile("ldmatrix.sync.aligned.m8n8.x4.trans.shared.b16 {%0,%1,%2,%3},[%4];" \
                 : "=r"(R0), "=r"(R1), "=r"(R2), "=r"(R3) : "r"(ADDR))
#define STS32(ADDR, V0) asm volatile("st.shared.b32 [%0],%1;" :: "r"(ADDR), "r"(V0))
#define CP16(saddr, gptr)                                                           \
    asm volatile("cp.async.cg.shared.global [%0], [%1], 16;" :: "r"(saddr), "l"(gptr))
#define CP_COMMIT() asm volatile("cp.async.commit_group;" ::: "memory")

// ---------------- prep kernels (one-time conversion) ----------------
__global__ void cvt_x(const float* __restrict__ in, __half* __restrict__ out, int n4) {
    int i = blockIdx.x * blockDim.x + threadIdx.x;
    if (i >= n4) return;
    float4 f = ((const float4*)in)[i];
    __half2 a = __floats2half2_rn(f.x, f.y);
    __half2 b = __floats2half2_rn(f.z, f.w);
    __half2* o = (__half2*)(out + (size_t)i * 4);
    o[0] = a; o[1] = b;
}

// w fp32 [4096][N] -> fp16 hi/lo planes [4096][ldo] at column offset co
__global__ void splitw(const float* __restrict__ w, int N4,
                       __half* __restrict__ wh, __half* __restrict__ wl,
                       int ldo, int co) {
    int i = blockIdx.x * blockDim.x + threadIdx.x;
    if (i >= 4096 * N4) return;
    int row = i / N4, c4 = i - row * N4;
    float4 f = ((const float4*)w)[i];
    __half2 h0 = __floats2half2_rn(f.x, f.y);
    __half2 h1 = __floats2half2_rn(f.z, f.w);
    float2 h0f = __half22float2(h0), h1f = __half22float2(h1);
    __half2 l0 = __floats2half2_rn(f.x - h0f.x, f.y - h0f.y);
    __half2 l1 = __floats2half2_rn(f.z - h1f.x, f.w - h1f.y);
    size_t off = (size_t)row * ldo + co + c4 * 4;
    ((__half2*)(wh + off))[0] = h0; ((__half2*)(wh + off))[1] = h1;
    ((__half2*)(wl + off))[0] = l0; ((__half2*)(wl + off))[1] = l1;
}

// ======================================================================
// preconverted fp16x2 GEMM: C[2048 x N] = A16 * (Bh + Bl).
// BM=128, BN=256, BK=64, 512 thr, warps 4(M)x4(N), warp tile 32x64.
// Pure cp.async mainloop, 2-deep, 64 stages.
// smem/stage: A 0..18432 (pitch 144) | Bh 18432..52224 (pitch 528) | Bl ..86016
#define W_STG 86016
#define W_BH  18432u
#define W_BL  52224u

template <bool OUTH>
__global__ void __launch_bounds__(512, 1) gemm_pc(
    const __half* __restrict__ A, int lda,
    const __half* __restrict__ Bh, const __half* __restrict__ Bl, int ldb,
    void* __restrict__ Cout, int ldc, int ropeLim,
    const float* __restrict__ cosp, const float* __restrict__ sinp)
{
    extern __shared__ char sh[];
    const int tid = threadIdx.x;
    const int lane = tid & 31, warp = tid >> 5;
    const int g = lane >> 2, t4 = lane & 3;
    const int wm = (warp & 3) * 32, wn = (warp >> 2) * 64;
    const int bm = blockIdx.y * 128, bn = blockIdx.x * 256;

    uint32_t sbase;
    asm("{ .reg .u64 t; cvta.to.shared.u64 t, %1; cvt.u32.u64 %0, t; }"
        : "=r"(sbase) : "l"(sh));

    // cp.async coords: A 2 chunks/thread (128 rows x 8 chunks), B 4+4 chunks/thread
    uint32_t aDst[2];
    const __half* aSrc[2];
#pragma unroll
    for (int j = 0; j < 2; j++) {
        int idx = tid + j * 512;
        int r = idx >> 3, c = idx & 7;
        aDst[j] = (uint32_t)(r * 144 + c * 16);
        aSrc[j] = A + (size_t)(bm + r) * lda + c * 8;
    }
    uint32_t bDst[4];
    const __half* bSrcH[4];
    const __half* bSrcL[4];
#pragma unroll
    for (int j = 0; j < 4; j++) {
        int idx = tid + j * 512;
        int kr = idx >> 5, c = idx & 31;
        bDst[j] = W_BH + (uint32_t)(kr * 528 + c * 16);
        bSrcH[j] = Bh + (size_t)kr * ldb + bn + c * 8;
        bSrcL[j] = Bl + (size_t)kr * ldb + bn + c * 8;
    }

    auto loadStage = [&](int t) {
        const uint32_t so = sbase + (uint32_t)(t & 1) * W_STG;
        const size_t ko = (size_t)t * 64;
#pragma unroll
        for (int j = 0; j < 2; j++) CP16(so + aDst[j], aSrc[j] + ko);
#pragma unroll
        for (int j = 0; j < 4; j++) {
            CP16(so + bDst[j], bSrcH[j] + ko * ldb);
            CP16(so + bDst[j] + (W_BL - W_BH), bSrcL[j] + ko * ldb);
        }
        CP_COMMIT();
    };

    const int lr = (lane & 7) + ((lane >> 3) & 1) * 8;
    const int lk = lane >> 4;
    uint32_t aAddr[2], bAddr[4];
#pragma unroll
    for (int mi = 0; mi < 2; mi++)
        aAddr[mi] = sbase + (uint32_t)((wm + mi * 16 + lr) * 144 + lk * 16);
#pragma unroll
    for (int nb = 0; nb < 4; nb++) {
        int kk = (lane & 7) + lk * 8;
        int nc = (wn >> 3) + nb * 2 + ((lane >> 3) & 1);
        bAddr[nb] = sbase + W_BH + (uint32_t)(kk * 528 + nc * 16);
    }

    float acc[2][8][4];
#pragma unroll
    for (int i = 0; i < 2; i++)
#pragma unroll
        for (int j = 0; j < 8; j++)
#pragma unroll
            for (int l = 0; l < 4; l++) acc[i][j][l] = 0.f;

    const int nK = 64;  // K = 4096, BK = 64
    loadStage(0);

    for (int t = 0; t < nK; t++) {
        asm volatile("cp.async.wait_group 0;" ::: "memory");
        __syncthreads();
        if (t + 1 < nK) loadStage(t + 1);
        const uint32_t so = (uint32_t)(t & 1) * W_STG;
#pragma unroll
        for (int kb = 0; kb < 4; kb++) {
            uint32_t AH[2][4], BH[8][2], BL[8][2];
#pragma unroll
            for (int mi = 0; mi < 2; mi++)
                LDSM4(AH[mi][0], AH[mi][1], AH[mi][2], AH[mi][3],
                      aAddr[mi] + so + kb * 32);
#pragma unroll
            for (int nb = 0; nb < 4; nb++) {
                uint32_t q0, q1, q2, q3;
                uint32_t bd = bAddr[nb] + so + kb * (16 * 528);
                LDSM4T(q0, q1, q2, q3, bd);
                BH[2 * nb][0] = q0; BH[2 * nb][1] = q2;
                BH[2 * nb + 1][0] = q1; BH[2 * nb + 1][1] = q3;
                LDSM4T(q0, q1, q2, q3, bd + (W_BL - W_BH));
                BL[2 * nb][0] = q0; BL[2 * nb][1] = q2;
                BL[2 * nb + 1][0] = q1; BL[2 * nb + 1][1] = q3;
            }
#pragma unroll
            for (int mi = 0; mi < 2; mi++)
#pragma unroll
                for (int ni = 0; ni < 8; ni++) {
                    MMAH16816(acc[mi][ni], AH[mi][0], AH[mi][1], AH[mi][2], AH[mi][3],
                              BL[ni][0], BL[ni][1]);
                    MMAH16816(acc[mi][ni], AH[mi][0], AH[mi][1], AH[mi][2], AH[mi][3],
                              BH[ni][0], BH[ni][1]);
                }
        }
    }

#pragma unroll
    for (int mi = 0; mi < 2; mi++) {
        int rowg = bm + wm + mi * 16 + g;
#pragma unroll
        for (int ni = 0; ni < 8; ni++) {
            int colg = bn + wn + ni * 8 + 2 * t4;
            float c0 = acc[mi][ni][0], c1 = acc[mi][ni][1];
            float c2 = acc[mi][ni][2], c3 = acc[mi][ni][3];
            if (colg < ropeLim) {
                int i = (colg & 127) >> 1;
                float cs = cosp[rowg * 64 + i], sn = sinp[rowg * 64 + i];
                float cs2 = cosp[(rowg + 8) * 64 + i], sn2 = sinp[(rowg + 8) * 64 + i];
                float o0 = c0 * cs - c1 * sn, o1 = c0 * sn + c1 * cs;
                float o2 = c2 * cs2 - c3 * sn2, o3 = c2 * sn2 + c3 * cs2;
                c0 = o0; c1 = o1; c2 = o2; c3 = o3;
            }
            if (OUTH) {
                __half* Ch = (__half*)Cout;
                *(__half2*)(Ch + (size_t)rowg * ldc + colg) = __floats2half2_rn(c0, c1);
                *(__half2*)(Ch + (size_t)(rowg + 8) * ldc + colg) = __floats2half2_rn(c2, c3);
            } else {
                float* Cf = (float*)Cout;
                *(float2*)(Cf + (size_t)rowg * ldc + colg) = make_float2(c0, c1);
                *(float2*)(Cf + (size_t)(rowg + 8) * ldc + colg) = make_float2(c2, c3);
            }
        }
    }
}

// ======== flash attention (K/V from merged [2048][2048] buffer; O -> fp16) ====
#define FK_K   34816u
#define FK_V   104448u
#define FK_P   139264u
#define FK_RED 174080u
#define FK_SM  178176

__global__ void __launch_bounds__(512, 1) flash_k(
    const __half* __restrict__ Qm, const __half* __restrict__ KVm,
    __half* __restrict__ Oh, float scale)
{
    extern __shared__ char sh[];
    const int h = blockIdx.y;
    const int bm = blockIdx.x * 128;
    const int tid = threadIdx.x;
    const int lane = tid & 31, warp = tid >> 5;
    const int g = lane >> 2, t4 = lane & 3;
    const int wm = (warp & 3) * 32, wn = (warp >> 2) * 32;
    const int wN = warp >> 2;

    uint32_t sbase;
    asm("{ .reg .u64 t; cvta.to.shared.u64 t, %1; cvt.u32.u64 %0, t; }"
        : "=r"(sbase) : "l"(sh));
    float* redM = (float*)(sh + FK_RED);
    float* redS = redM + 512;

    const __half* Qg = Qm + (size_t)bm * 4096 + h * 128;
    const __half* Kg = KVm + (size_t)(h >> 2) * 128;
    const __half* Vg = KVm + 1024 + (size_t)(h >> 2) * 128;

#pragma unroll
    for (int j = 0; j < 4; j++) {
        int idx = tid + j * 512;
        int r = idx >> 4, c = idx & 15;
        CP16(sbase + (uint32_t)(r * 272 + c * 16), Qg + (size_t)r * 4096 + c * 8);
    }
    CP_COMMIT();

    auto cpK = [&](int t) {
        uint32_t dst = sbase + FK_K + (uint32_t)(t & 1) * 34816u;
        const __half* src = Kg + (size_t)t * 128 * 2048;
#pragma unroll
        for (int j = 0; j < 4; j++) {
            int idx = tid + j * 512;
            int r = idx >> 4, c = idx & 15;
            CP16(dst + (uint32_t)(r * 272 + c * 16), src + (size_t)r * 2048 + c * 8);
        }
        CP_COMMIT();
    };
    auto cpV = [&](int t) {
        uint32_t dst = sbase + FK_V;
        const __half* src = Vg + (size_t)t * 128 * 2048;
#pragma unroll
        for (int j = 0; j < 4; j++) {
            int idx = tid + j * 512;
            int r = idx >> 4, c = idx & 15;
            CP16(dst + (uint32_t)(r * 272 + c * 16), src + (size_t)r * 2048 + c * 8);
        }
        CP_COMMIT();
    };
    cpK(0);
    cpV(0);

    const int lr = (lane & 7) + ((lane >> 3) & 1) * 8;
    const int lk = lane >> 4;
    uint32_t qAddr[2], pAddr[2], kAddr[2], vAddr[2];
#pragma unroll
    for (int mi = 0; mi < 2; mi++) {
        qAddr[mi] = sbase + (uint32_t)((wm + mi * 16 + lr) * 272 + lk * 16);
        pAddr[mi] = sbase + FK_P + (uint32_t)((wm + mi * 16 + lr) * 272 + lk * 16);
    }
#pragma unroll
    for (int nb = 0; nb < 2; nb++) {
        kAddr[nb] = sbase + FK_K + (uint32_t)((wn + nb * 16 + lr) * 272 + lk * 16);
        vAddr[nb] = sbase + FK_V +
                    (uint32_t)(((lane & 7) + lk * 8) * 272 +
                               ((wn >> 3) + nb * 2 + ((lane >> 3) & 1)) * 16);
    }

    float accO[2][4][4];
#pragma unroll
    for (int i = 0; i < 2; i++)
#pragma unroll
        for (int j = 0; j < 4; j++)
#pragma unroll
            for (int l = 0; l < 4; l++) accO[i][j][l] = 0.f;
    float mrow[2][2] = {{-1e30f, -1e30f}, {-1e30f, -1e30f}};
    float lsum[2][2] = {{0.f, 0.f}, {0.f, 0.f}};

    for (int t = 0; t < 16; t++) {
        asm volatile("cp.async.wait_group 1;" ::: "memory");
        __syncthreads();

        float accS[2][4][4];
#pragma unroll
        for (int i = 0; i < 2; i++)
#pragma unroll
            for (int j = 0; j < 4; j++)
#pragma unroll
                for (int l = 0; l < 4; l++) accS[i][j][l] = 0.f;
        const uint32_t kst = (uint32_t)(t & 1) * 34816u;
#pragma unroll
        for (int kk = 0; kk < 8; kk++) {
            uint32_t QA[2][4], KB[4][2];
#pragma unroll
            for (int mi = 0; mi < 2; mi++)
                LDSM4(QA[mi][0], QA[mi][1], QA[mi][2], QA[mi][3], qAddr[mi] + kk * 32);
#pragma unroll
            for (int nb = 0; nb < 2; nb++) {
                uint32_t q0, q1, q2, q3;
                LDSM4(q0, q1, q2, q3, kAddr[nb] + kst + kk * 32);
                KB[2 * nb][0] = q0; KB[2 * nb][1] = q2;
                KB[2 * nb + 1][0] = q1; KB[2 * nb + 1][1] = q3;
            }
#pragma unroll
            for (int mi = 0; mi < 2; mi++)
#pragma unroll
                for (int ni = 0; ni < 4; ni++)
                    MMAH16816(accS[mi][ni], QA[mi][0], QA[mi][1], QA[mi][2], QA[mi][3],
                              KB[ni][0], KB[ni][1]);
        }
        if (t < 15) cpK(t + 1);

        float tm[2][2] = {{-1e30f, -1e30f}, {-1e30f, -1e30f}};
#pragma unroll
        for (int mi = 0; mi < 2; mi++)
#pragma unroll
            for (int ni = 0; ni < 4; ni++) {
                accS[mi][ni][0] *= scale; accS[mi][ni][1] *= scale;
                accS[mi][ni][2] *= scale; accS[mi][ni][3] *= scale;
                tm[mi][0] = fmaxf(tm[mi][0], fmaxf(accS[mi][ni][0], accS[mi][ni][1]));
                tm[mi][1] = fmaxf(tm[mi][1], fmaxf(accS[mi][ni][2], accS[mi][ni][3]));
            }
#pragma unroll
        for (int mi = 0; mi < 2; mi++)
#pragma unroll
            for (int hh = 0; hh < 2; hh++) {
                tm[mi][hh] = fmaxf(tm[mi][hh], __shfl_xor_sync(0xffffffffu, tm[mi][hh], 1));
                tm[mi][hh] = fmaxf(tm[mi][hh], __shfl_xor_sync(0xffffffffu, tm[mi][hh], 2));
            }
        if (t4 == 0)
#pragma unroll
            for (int mi = 0; mi < 2; mi++)
#pragma unroll
                for (int hh = 0; hh < 2; hh++)
                    redM[wN * 128 + wm + mi * 16 + g + hh * 8] = tm[mi][hh];
        __syncthreads();

        float Mn[2][2], al[2][2];
#pragma unroll
        for (int mi = 0; mi < 2; mi++)
#pragma unroll
            for (int hh = 0; hh < 2; hh++) {
                int row = wm + mi * 16 + g + hh * 8;
                float m = fmaxf(fmaxf(redM[row], redM[128 + row]),
                                fmaxf(redM[256 + row], redM[384 + row]));
                Mn[mi][hh] = fmaxf(mrow[mi][hh], m);
                al[mi][hh] = __expf(mrow[mi][hh] - Mn[mi][hh]);
                mrow[mi][hh] = Mn[mi][hh];
            }

        float rs[2][2] = {{0.f, 0.f}, {0.f, 0.f}};
#pragma unroll
        for (int mi = 0; mi < 2; mi++)
#pragma unroll
            for (int ni = 0; ni < 4; ni++) {
                float p0 = __expf(accS[mi][ni][0] - Mn[mi][0]);
                float p1 = __expf(accS[mi][ni][1] - Mn[mi][0]);
                float p2 = __expf(accS[mi][ni][2] - Mn[mi][1]);
                float p3 = __expf(accS[mi][ni][3] - Mn[mi][1]);
                rs[mi][0] += p0 + p1;
                rs[mi][1] += p2 + p3;
                __half2 hA = __floats2half2_rn(p0, p1);
                __half2 hB = __floats2half2_rn(p2, p3);
                uint32_t a0 = sbase + FK_P +
                              (uint32_t)((wm + mi * 16 + g) * 272 + (wn + ni * 8 + 2 * t4) * 2);
                STS32(a0, *(uint32_t*)&hA);
                STS32(a0 + 8 * 272, *(uint32_t*)&hB);
            }
#pragma unroll
        for (int mi = 0; mi < 2; mi++)
#pragma unroll
            for (int hh = 0; hh < 2; hh++) {
                rs[mi][hh] += __shfl_xor_sync(0xffffffffu, rs[mi][hh], 1);
                rs[mi][hh] += __shfl_xor_sync(0xffffffffu, rs[mi][hh], 2);
            }
        if (t4 == 0)
#pragma unroll
            for (int mi = 0; mi < 2; mi++)
#pragma unroll
                for (int hh = 0; hh < 2; hh++)
                    redS[wN * 128 + wm + mi * 16 + g + hh * 8] = rs[mi][hh];
        if (t < 15) asm volatile("cp.async.wait_group 1;" ::: "memory");
        else        asm volatile("cp.async.wait_group 0;" ::: "memory");
        __syncthreads();

#pragma unroll
        for (int mi = 0; mi < 2; mi++)
#pragma unroll
            for (int hh = 0; hh < 2; hh++) {
                int row = wm + mi * 16 + g + hh * 8;
                float rsum = redS[row] + redS[128 + row] + redS[256 + row] + redS[384 + row];
                lsum[mi][hh] = lsum[mi][hh] * al[mi][hh] + rsum;
            }
#pragma unroll
        for (int mi = 0; mi < 2; mi++)
#pragma unroll
            for (int ni = 0; ni < 4; ni++) {
                accO[mi][ni][0] *= al[mi][0]; accO[mi][ni][1] *= al[mi][0];
                accO[mi][ni][2] *= al[mi][1]; accO[mi][ni][3] *= al[mi][1];
            }

#pragma unroll
        for (int kk = 0; kk < 8; kk++) {
            uint32_t PA[2][4], VB[4][2];
#pragma unroll
            for (int mi = 0; mi < 2; mi++)
                LDSM4(PA[mi][0], PA[mi][1], PA[mi][2], PA[mi][3], pAddr[mi] + kk * 32);
#pragma unroll
            for (int nb = 0; nb < 2; nb++) {
                uint32_t q0, q1, q2, q3;
                LDSM4T(q0, q1, q2, q3, vAddr[nb] + kk * (16 * 272));
                VB[2 * nb][0] = q0; VB[2 * nb][1] = q2;
                VB[2 * nb + 1][0] = q1; VB[2 * nb + 1][1] = q3;
            }
#pragma unroll
            for (int mi = 0; mi < 2; mi++)
#pragma unroll
                for (int ni = 0; ni < 4; ni++)
                    MMAH16816(accO[mi][ni], PA[mi][0], PA[mi][1], PA[mi][2], PA[mi][3],
                              VB[ni][0], VB[ni][1]);
        }
        __syncthreads();
        if (t < 15) cpV(t + 1);
    }

    float inv[2][2];
#pragma unroll
    for (int mi = 0; mi < 2; mi++)
#pragma unroll
        for (int hh = 0; hh < 2; hh++) inv[mi][hh] = 1.0f / lsum[mi][hh];
#pragma unroll
    for (int mi = 0; mi < 2; mi++) {
        int rowg = bm + wm + mi * 16 + g;
#pragma unroll
        for (int ni = 0; ni < 4; ni++) {
            int colg = h * 128 + wn + ni * 8 + 2 * t4;
            *(__half2*)(Oh + (size_t)rowg * 4096 + colg) =
                __floats2half2_rn(accO[mi][ni][0] * inv[mi][0], accO[mi][ni][1] * inv[mi][0]);
            *(__half2*)(Oh + (size_t)(rowg + 8) * 4096 + colg) =
                __floats2half2_rn(accO[mi][ni][2] * inv[mi][1], accO[mi][ni][3] * inv[mi][1]);
        }
    }
}

extern "C" void kernel_launch(void* const* d_in, const int* in_sizes, int n_in,
                              void* d_out, int out_size) {
    const float* x  = (const float*)d_in[0];
    const float* fc = (const float*)d_in[1];
    const float* fs = (const float*)d_in[2];
    const float* wq = (const float*)d_in[3];
    const float* wk = (const float*)d_in[4];
    const float* wv = (const float*)d_in[5];
    const float* wo = (const float*)d_in[6];
    float* out = (float*)d_out;

    __half *xh, *wqh, *wql, *wkvh, *wkvl, *woh, *wol, *qh, *kvh, *ohh;
    cudaGetSymbolAddress((void**)&xh,   g_xh);
    cudaGetSymbolAddress((void**)&wqh,  g_wqh);  cudaGetSymbolAddress((void**)&wql,  g_wql);
    cudaGetSymbolAddress((void**)&wkvh, g_wkvh); cudaGetSymbolAddress((void**)&wkvl, g_wkvl);
    cudaGetSymbolAddress((void**)&woh,  g_woh);  cudaGetSymbolAddress((void**)&wol,  g_wol);
    cudaGetSymbolAddress((void**)&qh,   g_qh);
    cudaGetSymbolAddress((void**)&kvh,  g_kvh);
    cudaGetSymbolAddress((void**)&ohh,  g_ohh);

    const int SMW = 2 * W_STG;  // 172032
    cudaFuncSetAttribute(gemm_pc<true >, cudaFuncAttributeMaxDynamicSharedMemorySize, SMW);
    cudaFuncSetAttribute(gemm_pc<false>, cudaFuncAttributeMaxDynamicSharedMemorySize, SMW);
    cudaFuncSetAttribute(flash_k, cudaFuncAttributeMaxDynamicSharedMemorySize, FK_SM);

    const dim3 blk(512);
    const float scale = 0.08838834764831845f;  // 1/sqrt(128)

    // prep: fp16 planes
    cvt_x<<<8192, 256>>>(x, xh, SEQ * 4096 / 4);
    splitw<<<16384, 256>>>(wq, 1024, wqh, wql, 4096, 0);
    splitw<<< 4096, 256>>>(wk,  256, wkvh, wkvl, 2048, 0);
    splitw<<< 4096, 256>>>(wv,  256, wkvh, wkvl, 2048, 1024);
    splitw<<<16384, 256>>>(wo, 1024, woh, wol, 4096, 0);

    // projections
    gemm_pc<true ><<<dim3(16, 16), blk, SMW>>>(xh, 4096, wqh, wql, 4096, qh, 4096, 4096, fc, fs);
    gemm_pc<true ><<<dim3( 8, 16), blk, SMW>>>(xh, 4096, wkvh, wkvl, 2048, kvh, 2048, 1024, fc, fs);
    // attention
    flash_k<<<dim3(16, NHEADS), blk, FK_SM>>>(qh, kvh, ohh, scale);
    // output projection
    gemm_pc<false><<<dim3(16, 16), blk, SMW>>>(ohh, 4096, woh, wol, 4096, out, 4096, 0, nullptr, nullptr);
}